// round 2
// baseline (speedup 1.0000x reference)
#include <cuda_runtime.h>
#include <cuda_bf16.h>
#include <math.h>

#define BB    2
#define SS    4096
#define HIDN  2048
#define HVN   32
#define HKN   16
#define CONVD 8192
#define KEYD  2048
#define VALD  4096
#define NCHK  64
#define MROWS (BB*SS)

// ---------------- device scratch ----------------
__device__ float g_mixed[(size_t)BB*SS*CONVD];   // qkv mixed; later reused as gated activation
__device__ float g_z    [(size_t)BB*SS*VALD];
__device__ float g_qn   [(size_t)BB*HKN*SS*128];
__device__ float g_kn   [(size_t)BB*HKN*SS*128];
__device__ float g_v    [(size_t)BB*HVN*SS*128];
__device__ float g_core [(size_t)BB*HVN*SS*128];
__device__ float g_beta [(size_t)BB*SS*HVN];
__device__ float g_gg   [(size_t)BB*SS*HVN];

// ---------------- SGEMM: C[M,N] = A[M,K] @ B[K,N], fp32 row-major ----------------
// 128x128 tile, BK=8, 256 threads, 8x8 microtile. M,N mult of 128; K mult of 8.
__global__ __launch_bounds__(256) void sgemm_kernel(
    const float* __restrict__ A, const float* __restrict__ B, float* __restrict__ C,
    int M, int N, int K)
{
    __shared__ float As[8][132];
    __shared__ float Bs[8][128];
    int bx = blockIdx.x, by = blockIdx.y;
    int t = threadIdx.x;
    int tm = (t >> 4) * 8;
    int tn = (t & 15) * 8;

    const float* Aptr = A + (size_t)(by*128 + (t >> 1)) * K + (t & 1) * 4;
    const float* Bptr = B + (size_t)(t >> 5) * N + bx*128 + (t & 31) * 4;
    int ar = t >> 1, ac = (t & 1) * 4;

    float acc[8][8];
#pragma unroll
    for (int i = 0; i < 8; i++)
#pragma unroll
        for (int j = 0; j < 8; j++) acc[i][j] = 0.f;

    for (int k0 = 0; k0 < K; k0 += 8) {
        float4 av = *(const float4*)Aptr;
        float4 bv = *(const float4*)Bptr;
        As[ac+0][ar] = av.x; As[ac+1][ar] = av.y; As[ac+2][ar] = av.z; As[ac+3][ar] = av.w;
        *(float4*)&Bs[t >> 5][(t & 31) * 4] = bv;
        __syncthreads();
#pragma unroll
        for (int kk = 0; kk < 8; kk++) {
            float a[8], b[8];
            float4 a0 = *(const float4*)&As[kk][tm];
            float4 a1 = *(const float4*)&As[kk][tm+4];
            float4 b0 = *(const float4*)&Bs[kk][tn];
            float4 b1 = *(const float4*)&Bs[kk][tn+4];
            a[0]=a0.x;a[1]=a0.y;a[2]=a0.z;a[3]=a0.w;a[4]=a1.x;a[5]=a1.y;a[6]=a1.z;a[7]=a1.w;
            b[0]=b0.x;b[1]=b0.y;b[2]=b0.z;b[3]=b0.w;b[4]=b1.x;b[5]=b1.y;b[6]=b1.z;b[7]=b1.w;
#pragma unroll
            for (int i = 0; i < 8; i++)
#pragma unroll
                for (int j = 0; j < 8; j++) acc[i][j] += a[i] * b[j];
        }
        __syncthreads();
        Aptr += 8;
        Bptr += (size_t)8 * N;
    }
#pragma unroll
    for (int i = 0; i < 8; i++) {
        float* cp = C + (size_t)(by*128 + tm + i) * N + bx*128 + tn;
#pragma unroll
        for (int j = 0; j < 8; j += 4) {
            float4 v; v.x = acc[i][j]; v.y = acc[i][j+1]; v.z = acc[i][j+2]; v.w = acc[i][j+3];
            *(float4*)(cp + j) = v;
        }
    }
}

// ---------------- beta / g projections ----------------
#define BG_RG 4
__global__ __launch_bounds__(256) void bg_kernel(
    const float* __restrict__ hs, const float* __restrict__ W_b, const float* __restrict__ W_a,
    const float* __restrict__ dt_bias, const float* __restrict__ A_log,
    float* __restrict__ beta, float* __restrict__ gg)
{
    __shared__ float hsm[BG_RG * HIDN];
    __shared__ float red[4 * BG_RG * 64];
    int r0 = blockIdx.x * BG_RG;
    int t = threadIdx.x;
    for (int o = t; o < BG_RG * HIDN / 4; o += 256)
        ((float4*)hsm)[o] = ((const float4*)(hs + (size_t)r0 * HIDN))[o];
    __syncthreads();

    int out = t & 63, part = t >> 6;
    const float* Wp = (out < 32) ? (W_b + out) : (W_a + out - 32);
    float acc[BG_RG];
#pragma unroll
    for (int r = 0; r < BG_RG; r++) acc[r] = 0.f;
    int kbase = part * (HIDN / 4);
    for (int kk = 0; kk < HIDN / 4; kk++) {
        int k = kbase + kk;
        float w = Wp[(size_t)k * 32];
#pragma unroll
        for (int r = 0; r < BG_RG; r++) acc[r] += hsm[r * HIDN + k] * w;
    }
#pragma unroll
    for (int r = 0; r < BG_RG; r++) red[(part * BG_RG + r) * 64 + out] = acc[r];
    __syncthreads();

    int rr = t >> 6, oo = t & 63;
    float s = red[(0*BG_RG+rr)*64+oo] + red[(1*BG_RG+rr)*64+oo]
            + red[(2*BG_RG+rr)*64+oo] + red[(3*BG_RG+rr)*64+oo];
    size_t row = (size_t)r0 + rr;
    if (oo < 32) {
        beta[row * 32 + oo] = 1.f / (1.f + expf(-s));
    } else {
        int h = oo - 32;
        float x = s + dt_bias[h];
        float sp = (x > 20.f) ? x : log1pf(expf(x));
        gg[row * 32 + h] = -expf(A_log[h]) * sp;
    }
}

// ---------------- conv1d(K=4 causal) + SiLU + split + l2norm(q,k) ----------------
__global__ __launch_bounds__(128) void conv_silu_kernel(
    const float* __restrict__ mixed, const float* __restrict__ conv_w,
    float* __restrict__ qn, float* __restrict__ kn, float* __restrict__ vout)
{
    int unit = blockIdx.x;     // 0..63
    int s = blockIdx.y;        // 0..4095
    int b = blockIdx.z;        // 0..1
    int d = threadIdx.x;       // 0..127
    int base = (unit < 16) ? unit * 128
             : (unit < 32) ? KEYD + (unit - 16) * 128
             : 2 * KEYD + (unit - 32) * 128;
    int c = base + d;
    const float* mb = mixed + (size_t)b * SS * CONVD + c;
    float acc = 0.f;
#pragma unroll
    for (int j = 0; j < 4; j++) {
        int sp = s + j - 3;
        float x = (sp >= 0) ? mb[(size_t)sp * CONVD] : 0.f;
        acc += conv_w[(size_t)c * 4 + j] * x;
    }
    float xs = acc / (1.f + expf(-acc));   // SiLU

    if (unit < 32) {
        __shared__ float red[4];
        float ss = xs * xs;
#pragma unroll
        for (int off = 16; off > 0; off >>= 1) ss += __shfl_down_sync(0xffffffffu, ss, off);
        if ((d & 31) == 0) red[d >> 5] = ss;
        __syncthreads();
        float tot = red[0] + red[1] + red[2] + red[3];
        float scale = rsqrtf(tot + 1e-6f);
        if (unit < 16) {
            scale *= 0.08838834764831845f;  // DK^-0.5
            qn[(((size_t)(b * HKN + unit)) * SS + s) * 128 + d] = xs * scale;
        } else {
            kn[(((size_t)(b * HKN + unit - 16)) * SS + s) * 128 + d] = xs * scale;
        }
    } else {
        vout[(((size_t)(b * HVN + unit - 32)) * SS + s) * 128 + d] = xs;
    }
}

// ---------------- chunked gated delta rule: one block per (b,h) ----------------
// smem floats: st 16384 | KT 8320 | Qs 8192 | Vs 8192 | Wm 4096 | Am 4096 | 256 scalars
#define DELTA_SMEM_BYTES ((16384+8320+8192+8192+4096+4096+256)*4)

__global__ __launch_bounds__(256, 1) void delta_kernel(
    const float* __restrict__ qn, const float* __restrict__ kn,
    const float* __restrict__ vv, const float* __restrict__ beta,
    const float* __restrict__ gg, float* __restrict__ core)
{
    extern __shared__ float sm[];
    float* st  = sm;
    float* KT  = st + 16384;   // [128][65]
    float* Qs  = KT + 8320;    // [64][128]
    float* Vs  = Qs + 8192;    // [64][128]  v_beta -> X -> v_new
    float* Wm  = Vs + 8192;    // [64][64]
    float* Am  = Wm + 4096;    // [64][64]
    float* gcs = Am + 4096;    // 64
    float* bet = gcs + 64;
    float* egs = bet + 64;     // exp(gc)
    float* edl = egs + 64;     // exp(g_last - gc)

    int t = threadIdx.x;
    int b = blockIdx.x >> 5, h = blockIdx.x & 31, hk = h >> 1;
    const float* qb = qn + (size_t)(b*HKN+hk)*SS*128;
    const float* kb = kn + (size_t)(b*HKN+hk)*SS*128;
    const float* vb = vv + (size_t)(b*HVN+h)*SS*128;
    const float* bp = beta + (size_t)b*SS*HVN + h;
    const float* gp = gg   + (size_t)b*SS*HVN + h;
    float* cb = core + (size_t)(b*HVN+h)*SS*128;

    for (int i = t; i < 16384; i += 256) st[i] = 0.f;
    __syncthreads();

    for (int ck = 0; ck < NCHK; ck++) {
        size_t srow = (size_t)ck * 64;
        const float* qr = qb + srow*128;
        const float* kr = kb + srow*128;
        const float* vr = vb + srow*128;
        for (int idx = t; idx < 8192; idx += 256) {
            Qs[idx] = qr[idx];
            Vs[idx] = vr[idx];
            int i = idx >> 7, d = idx & 127;
            KT[d*65 + i] = kr[idx];
        }
        if (t < 64) {
            bet[t] = bp[(srow + t)*HVN];
            edl[t] = gp[(srow + t)*HVN];   // raw g, temp
        }
        __syncthreads();
        if (t == 0) {
            float r = 0.f;
            for (int i = 0; i < 64; i++) { r += edl[i]; gcs[i] = r; }
        }
        __syncthreads();
        if (t < 64) {
            egs[t] = expf(gcs[t]);
            edl[t] = expf(gcs[63] - gcs[t]);
        }
        __syncthreads();

        // ---- W[i][j] = beta_i*(k_i.k_j)*e^{gci-gcj} (j<i),  Am[i][j] = (q_i.k_j)*e^{gci-gcj} (j<=i)
        {
            int r0 = (t >> 3) * 2, c0 = (t & 7) * 8;
            float wa[2][8], aa[2][8];
#pragma unroll
            for (int i = 0; i < 2; i++)
#pragma unroll
                for (int j = 0; j < 8; j++) { wa[i][j] = 0.f; aa[i][j] = 0.f; }
            for (int d = 0; d < 128; d++) {
                float k0 = KT[d*65 + r0], k1 = KT[d*65 + r0 + 1];
                float q0 = Qs[r0*128 + d], q1 = Qs[(r0+1)*128 + d];
                const float* kj = &KT[d*65 + c0];
#pragma unroll
                for (int j = 0; j < 8; j++) {
                    float kv = kj[j];
                    wa[0][j] += k0*kv; wa[1][j] += k1*kv;
                    aa[0][j] += q0*kv; aa[1][j] += q1*kv;
                }
            }
#pragma unroll
            for (int ii = 0; ii < 2; ii++) {
                int i = r0 + ii; float bi = bet[i], gi = gcs[i];
#pragma unroll
                for (int j = 0; j < 8; j++) {
                    int jc = c0 + j;
                    float w = 0.f, a = 0.f;
                    if (jc <= i) {
                        float e = expf(gi - gcs[jc]);
                        a = e * aa[ii][j];
                        if (jc < i) w = bi * e * wa[ii][j];
                    }
                    Wm[i*64 + jc] = w;
                    Am[i*64 + jc] = a;
                }
            }
        }
        // ---- X = beta*(v - e^{gc} * (k @ st))   (overwrite Vs)
        {
            int r0 = (t >> 4) * 4, c0 = (t & 15) * 8;
            float acc[4][8];
#pragma unroll
            for (int i = 0; i < 4; i++)
#pragma unroll
                for (int j = 0; j < 8; j++) acc[i][j] = 0.f;
            for (int d = 0; d < 128; d++) {
                float kv[4];
#pragma unroll
                for (int i = 0; i < 4; i++) kv[i] = KT[d*65 + r0 + i];
                float4 s0 = *(float4*)&st[d*128 + c0];
                float4 s1 = *(float4*)&st[d*128 + c0 + 4];
                float sv[8] = {s0.x,s0.y,s0.z,s0.w,s1.x,s1.y,s1.z,s1.w};
#pragma unroll
                for (int i = 0; i < 4; i++)
#pragma unroll
                    for (int j = 0; j < 8; j++) acc[i][j] += kv[i]*sv[j];
            }
#pragma unroll
            for (int i = 0; i < 4; i++) {
                int r = r0 + i; float bi = bet[r], e = egs[r];
#pragma unroll
                for (int j = 0; j < 8; j++) {
                    int c = c0 + j;
                    Vs[r*128 + c] = bi*(Vs[r*128 + c] - e*acc[i][j]);
                }
            }
        }
        __syncthreads();
        // ---- forward substitution: v_new = (I+W)^{-1} X, column-parallel
        if (t < 128) {
            float x[64];
#pragma unroll
            for (int i = 0; i < 64; i++) {
                float a0 = Vs[i*128 + t], a1 = 0.f;
                int j = 0;
#pragma unroll
                for (; j + 2 <= i; j += 2) {
                    a0 -= Wm[i*64 + j]   * x[j];
                    a1 -= Wm[i*64 + j+1] * x[j+1];
                }
                if (j < i) a0 -= Wm[i*64 + j] * x[j];
                x[i] = a0 + a1;
            }
#pragma unroll
            for (int i = 0; i < 64; i++) Vs[i*128 + t] = x[i];
        }
        __syncthreads();
        // ---- out = e^{gc} * (q @ st) + Am @ v_new
        {
            int r0 = (t >> 4) * 4, c0 = (t & 15) * 8;
            float o1[4][8], o2[4][8];
#pragma unroll
            for (int i = 0; i < 4; i++)
#pragma unroll
                for (int j = 0; j < 8; j++) { o1[i][j] = 0.f; o2[i][j] = 0.f; }
            for (int d = 0; d < 128; d++) {
                float qv[4];
#pragma unroll
                for (int i = 0; i < 4; i++) qv[i] = Qs[(r0+i)*128 + d];
                float4 s0 = *(float4*)&st[d*128 + c0];
                float4 s1 = *(float4*)&st[d*128 + c0 + 4];
                float sv[8] = {s0.x,s0.y,s0.z,s0.w,s1.x,s1.y,s1.z,s1.w};
#pragma unroll
                for (int i = 0; i < 4; i++)
#pragma unroll
                    for (int j = 0; j < 8; j++) o1[i][j] += qv[i]*sv[j];
            }
            for (int jj = 0; jj < 64; jj++) {
                float av[4];
#pragma unroll
                for (int i = 0; i < 4; i++) av[i] = Am[(r0+i)*64 + jj];
                float4 v0 = *(float4*)&Vs[jj*128 + c0];
                float4 v1 = *(float4*)&Vs[jj*128 + c0 + 4];
                float vw[8] = {v0.x,v0.y,v0.z,v0.w,v1.x,v1.y,v1.z,v1.w};
#pragma unroll
                for (int i = 0; i < 4; i++)
#pragma unroll
                    for (int j = 0; j < 8; j++) o2[i][j] += av[i]*vw[j];
            }
#pragma unroll
            for (int i = 0; i < 4; i++) {
                int r = r0 + i; float e = egs[r];
#pragma unroll
                for (int j = 0; j < 8; j += 4) {
                    float4 v;
                    v.x = e*o1[i][j]   + o2[i][j];
                    v.y = e*o1[i][j+1] + o2[i][j+1];
                    v.z = e*o1[i][j+2] + o2[i][j+2];
                    v.w = e*o1[i][j+3] + o2[i][j+3];
                    *(float4*)&cb[(srow + r)*128 + c0 + j] = v;
                }
            }
        }
        __syncthreads();
        // ---- state update: st = st*e^{gl} + kd^T @ v_new
        {
            int d0 = (t >> 4) * 8, v0 = (t & 15) * 8;
            float acc[8][8];
#pragma unroll
            for (int i = 0; i < 8; i++)
#pragma unroll
                for (int j = 0; j < 8; j++) acc[i][j] = 0.f;
            for (int i = 0; i < 64; i++) {
                float el = edl[i];
                float kv[8];
#pragma unroll
                for (int x2 = 0; x2 < 8; x2++) kv[x2] = KT[(d0+x2)*65 + i] * el;
                float4 a = *(float4*)&Vs[i*128 + v0];
                float4 bq = *(float4*)&Vs[i*128 + v0 + 4];
                float vw[8] = {a.x,a.y,a.z,a.w,bq.x,bq.y,bq.z,bq.w};
#pragma unroll
                for (int x2 = 0; x2 < 8; x2++)
#pragma unroll
                    for (int y = 0; y < 8; y++) acc[x2][y] += kv[x2]*vw[y];
            }
            float egl = expf(gcs[63]);
#pragma unroll
            for (int x2 = 0; x2 < 8; x2++)
#pragma unroll
                for (int y = 0; y < 8; y += 4) {
                    float4 s = *(float4*)&st[(d0+x2)*128 + v0 + y];
                    s.x = s.x*egl + acc[x2][y];
                    s.y = s.y*egl + acc[x2][y+1];
                    s.z = s.z*egl + acc[x2][y+2];
                    s.w = s.w*egl + acc[x2][y+3];
                    *(float4*)&st[(d0+x2)*128 + v0 + y] = s;
                }
        }
        __syncthreads();
    }
}

// ---------------- gated RMSNorm + SiLU(z) gate -> activation for final GEMM ----------------
__global__ __launch_bounds__(128) void normgate_kernel(
    const float* __restrict__ core, const float* __restrict__ z,
    const float* __restrict__ norm_weight, float* __restrict__ act)
{
    int s = blockIdx.x, h = blockIdx.y, b = blockIdx.z;
    int d = threadIdx.x;
    __shared__ float red[4];
    size_t ci = ((size_t)(b*HVN + h)*SS + s)*128 + d;
    float v = core[ci];
    float ss = v*v;
#pragma unroll
    for (int off = 16; off > 0; off >>= 1) ss += __shfl_down_sync(0xffffffffu, ss, off);
    if ((d & 31) == 0) red[d >> 5] = ss;
    __syncthreads();
    float var = (red[0]+red[1]+red[2]+red[3]) * (1.f/128.f);
    float scale = rsqrtf(var + 1e-6f) * norm_weight[d];
    size_t zi = ((size_t)b*SS + s)*VALD + h*128 + d;
    float zv = z[zi];
    float gate = zv / (1.f + expf(-zv));
    act[zi] = v * scale * gate;
}

extern "C" void kernel_launch(void* const* d_in, const int* in_sizes, int n_in,
                              void* d_out, int out_size) {
    const float* hs     = (const float*)d_in[0];
    const float* W_qkv  = (const float*)d_in[1];
    const float* conv_w = (const float*)d_in[2];
    const float* W_z    = (const float*)d_in[3];
    const float* W_b    = (const float*)d_in[4];
    const float* W_a    = (const float*)d_in[5];
    const float* dt_b   = (const float*)d_in[6];
    const float* A_log  = (const float*)d_in[7];
    const float* normw  = (const float*)d_in[8];
    const float* W_out  = (const float*)d_in[9];
    float* out = (float*)d_out;

    float *mixed, *z, *qn, *kn, *v, *core, *beta, *gg;
    cudaGetSymbolAddress((void**)&mixed, g_mixed);
    cudaGetSymbolAddress((void**)&z,     g_z);
    cudaGetSymbolAddress((void**)&qn,    g_qn);
    cudaGetSymbolAddress((void**)&kn,    g_kn);
    cudaGetSymbolAddress((void**)&v,     g_v);
    cudaGetSymbolAddress((void**)&core,  g_core);
    cudaGetSymbolAddress((void**)&beta,  g_beta);
    cudaGetSymbolAddress((void**)&gg,    g_gg);

    cudaFuncSetAttribute(delta_kernel, cudaFuncAttributeMaxDynamicSharedMemorySize, DELTA_SMEM_BYTES);

    // 1) mixed = hs @ W_qkv
    sgemm_kernel<<<dim3(CONVD/128, MROWS/128), 256>>>(hs, W_qkv, mixed, MROWS, CONVD, HIDN);
    // 2) z = hs @ W_z
    sgemm_kernel<<<dim3(VALD/128, MROWS/128), 256>>>(hs, W_z, z, MROWS, VALD, HIDN);
    // 3) beta, g
    bg_kernel<<<MROWS/BG_RG, 256>>>(hs, W_b, W_a, dt_b, A_log, beta, gg);
    // 4) conv + silu + split + l2norm
    conv_silu_kernel<<<dim3(64, SS, BB), 128>>>(mixed, conv_w, qn, kn, v);
    // 5) chunked gated delta rule
    delta_kernel<<<BB*HVN, 256, DELTA_SMEM_BYTES>>>(qn, kn, v, beta, gg, core);
    // 6) gated rmsnorm * silu(z) -> act (reuse mixed buffer)
    normgate_kernel<<<dim3(SS, HVN, BB), 128>>>(core, z, normw, mixed);
    // 7) out = act @ W_out
    sgemm_kernel<<<dim3(HIDN/128, MROWS/128), 256>>>(mixed, W_out, out, MROWS, HIDN, VALD);
}

// round 6
// speedup vs baseline: 1.9057x; 1.9057x over previous
#include <cuda_runtime.h>
#include <cuda_bf16.h>
#include <math.h>
#include <stdint.h>

#define BB    2
#define SS    4096
#define HIDN  2048
#define HVN   32
#define HKN   16
#define CONVD 8192
#define KEYD  2048
#define VALD  4096
#define NCHK  64
#define MROWS (BB*SS)

// ---------------- device scratch ----------------
__device__ float g_mixed[(size_t)BB*SS*CONVD];
__device__ float g_z    [(size_t)BB*SS*VALD];
__device__ float g_qn   [(size_t)BB*HKN*SS*128];
__device__ float g_kn   [(size_t)BB*HKN*SS*128];
__device__ float g_v    [(size_t)BB*HVN*SS*128];
__device__ float g_core [(size_t)BB*HVN*SS*128];
__device__ float g_beta [(size_t)BB*SS*HVN];
__device__ float g_gg   [(size_t)BB*SS*HVN];

__device__ __nv_bfloat16 g_hs_hi [(size_t)MROWS*HIDN];
__device__ __nv_bfloat16 g_hs_lo [(size_t)MROWS*HIDN];
__device__ __nv_bfloat16 g_wqkv_hi[(size_t)CONVD*HIDN];  // [N,K]
__device__ __nv_bfloat16 g_wqkv_lo[(size_t)CONVD*HIDN];
__device__ __nv_bfloat16 g_wz_hi  [(size_t)VALD*HIDN];
__device__ __nv_bfloat16 g_wz_lo  [(size_t)VALD*HIDN];
__device__ __nv_bfloat16 g_wout_hi[(size_t)HIDN*VALD];
__device__ __nv_bfloat16 g_wout_lo[(size_t)HIDN*VALD];
__device__ __nv_bfloat16 g_act_hi [(size_t)MROWS*VALD];
__device__ __nv_bfloat16 g_act_lo [(size_t)MROWS*VALD];

// ---------------- helpers ----------------
__device__ __forceinline__ uint32_t smem_u32(const void* p) {
    uint32_t a;
    asm("{ .reg .u64 t; cvta.to.shared.u64 t, %1; cvt.u32.u64 %0, t; }" : "=r"(a) : "l"(p));
    return a;
}
__device__ __forceinline__ void ldsm4(uint32_t* r, uint32_t addr) {
    asm volatile("ldmatrix.sync.aligned.m8n8.x4.shared.b16 {%0,%1,%2,%3}, [%4];"
        : "=r"(r[0]), "=r"(r[1]), "=r"(r[2]), "=r"(r[3]) : "r"(addr));
}
__device__ __forceinline__ void mma16816(float* c, const uint32_t* a, const uint32_t* b) {
    asm volatile("mma.sync.aligned.m16n8k16.row.col.f32.bf16.bf16.f32 "
        "{%0,%1,%2,%3}, {%4,%5,%6,%7}, {%8,%9}, {%0,%1,%2,%3};"
        : "+f"(c[0]), "+f"(c[1]), "+f"(c[2]), "+f"(c[3])
        : "r"(a[0]), "r"(a[1]), "r"(a[2]), "r"(a[3]), "r"(b[0]), "r"(b[1]));
}
__device__ __forceinline__ void cp16(uint32_t dst, const void* src) {
    asm volatile("cp.async.cg.shared.global [%0], [%1], 16;" :: "r"(dst), "l"(src));
}

// ---------------- split kernels ----------------
__global__ __launch_bounds__(256) void split_kernel(
    const float* __restrict__ in, __nv_bfloat16* __restrict__ hi, __nv_bfloat16* __restrict__ lo, size_t n)
{
    size_t i = (size_t)blockIdx.x * 256 + threadIdx.x;
    size_t stride = (size_t)gridDim.x * 256;
    for (; i < n; i += stride) {
        float v = in[i];
        __nv_bfloat16 h = __float2bfloat16_rn(v);
        hi[i] = h;
        lo[i] = __float2bfloat16_rn(v - __bfloat162float(h));
    }
}

// W[K,N] -> [N,K] hi/lo
__global__ __launch_bounds__(256) void tsplit_kernel(
    const float* __restrict__ W, __nv_bfloat16* __restrict__ Thi, __nv_bfloat16* __restrict__ Tlo,
    int K, int N)
{
    __shared__ float tile[32][33];
    int tx = threadIdx.x & 31, ty = threadIdx.x >> 5;
    int bx = blockIdx.x, by = blockIdx.y;
    for (int i = ty; i < 32; i += 8)
        tile[i][tx] = W[(size_t)(by*32 + i) * N + bx*32 + tx];
    __syncthreads();
    for (int i = ty; i < 32; i += 8) {
        float v = tile[tx][i];
        __nv_bfloat16 h = __float2bfloat16_rn(v);
        size_t oi = (size_t)(bx*32 + i) * K + by*32 + tx;
        Thi[oi] = h;
        Tlo[oi] = __float2bfloat16_rn(v - __bfloat162float(h));
    }
}

// ---------------- HMMA bf16x3 GEMM: C[M,N] = A @ B^T ----------------
// A hi/lo [M,K] bf16; B hi/lo [N,K] bf16; C fp32. Tile 128x128x32, 256 thr.
// smem row = 32 bf16 data padded to 40 (80B). stage = 4 arrays * 128 rows * 80B = 40960B, x2.
#define GS_ROW   80           // bytes per smem row
#define GS_ARR   (128*GS_ROW) // 10240
#define GS_STAGE (4*GS_ARR)   // 40960
#define GEMM_SMEM (2*GS_STAGE)

__global__ __launch_bounds__(256) void hmma_gemm_kernel(
    const __nv_bfloat16* __restrict__ Ahi, const __nv_bfloat16* __restrict__ Alo,
    const __nv_bfloat16* __restrict__ Bhi, const __nv_bfloat16* __restrict__ Blo,
    float* __restrict__ C, int M, int N, int K)
{
    extern __shared__ char smem[];
    uint32_t sb = smem_u32(smem);
    int t = threadIdx.x;
    int m0 = blockIdx.x * 128;     // M fast-varying: A slab stays in L2
    int n0 = blockIdx.y * 128;
    int w = t >> 5, l = t & 31;
    int wm = w & 3, wn = w >> 2;   // 4 warps along M (32 rows), 2 along N (64 cols)

    const __nv_bfloat16* srcs[4] = { Ahi, Alo, Bhi, Blo };
    int rowbase[4];
    rowbase[0] = m0; rowbase[1] = m0; rowbase[2] = n0; rowbase[3] = n0;

    float acc[2][8][4];
#pragma unroll
    for (int i = 0; i < 2; i++)
#pragma unroll
        for (int j = 0; j < 8; j++)
#pragma unroll
            for (int r = 0; r < 4; r++) acc[i][j][r] = 0.f;

    int KT = K >> 5;

    auto load_stage = [&](int s, int k0) {
        uint32_t stb = sb + s * GS_STAGE;
#pragma unroll
        for (int c = 0; c < 8; c++) {
            int idx = t + c * 256;          // 0..2047
            int arr = idx >> 9;             // 0..3
            int within = idx & 511;
            int row = within >> 2, ch = within & 3;
            const __nv_bfloat16* src = srcs[arr] + (size_t)(rowbase[arr] + row) * K + k0 + ch * 8;
            cp16(stb + arr * GS_ARR + row * GS_ROW + ch * 16, src);
        }
        asm volatile("cp.async.commit_group;");
    };

    load_stage(0, 0);

    int a_off = (wm * 32 + (l & 15)) * GS_ROW + ((l >> 4) * 16);
    int b_off = (wn * 64 + (l & 7) + ((l >> 4) << 3)) * GS_ROW + (((l >> 3) & 1) * 16);

    for (int kt = 0; kt < KT; kt++) {
        if (kt + 1 < KT) load_stage((kt + 1) & 1, (kt + 1) << 5);
        if (kt + 1 < KT) asm volatile("cp.async.wait_group 1;");
        else             asm volatile("cp.async.wait_group 0;");
        __syncthreads();

        uint32_t stb = sb + (kt & 1) * GS_STAGE;
#pragma unroll
        for (int ks = 0; ks < 2; ks++) {
            uint32_t ah[2][4], al[2][4];
#pragma unroll
            for (int mt = 0; mt < 2; mt++) {
                uint32_t aa = stb + a_off + mt * 16 * GS_ROW + ks * 32;
                ldsm4(ah[mt], aa);                 // Ahi
                ldsm4(al[mt], aa + GS_ARR);        // Alo
            }
#pragma unroll
            for (int ntp = 0; ntp < 4; ntp++) {
                uint32_t ba = stb + 2 * GS_ARR + b_off + ntp * 16 * GS_ROW + ks * 32;
                uint32_t bh[4], bl[4];
                ldsm4(bh, ba);                     // Bhi (2 n-tiles)
                ldsm4(bl, ba + GS_ARR);            // Blo
#pragma unroll
                for (int mt = 0; mt < 2; mt++) {
                    mma16816(acc[mt][2*ntp],   ah[mt], bh);
                    mma16816(acc[mt][2*ntp],   ah[mt], bl);
                    mma16816(acc[mt][2*ntp],   al[mt], bh);
                    mma16816(acc[mt][2*ntp+1], ah[mt], bh + 2);
                    mma16816(acc[mt][2*ntp+1], ah[mt], bl + 2);
                    mma16816(acc[mt][2*ntp+1], al[mt], bh + 2);
                }
            }
        }
        __syncthreads();
    }

    // epilogue
#pragma unroll
    for (int mt = 0; mt < 2; mt++) {
        int row = m0 + wm * 32 + mt * 16 + (l >> 2);
        int colb = n0 + wn * 64 + 2 * (l & 3);
#pragma unroll
        for (int nt = 0; nt < 8; nt++) {
            int col = colb + nt * 8;
            float2 v0; v0.x = acc[mt][nt][0]; v0.y = acc[mt][nt][1];
            float2 v1; v1.x = acc[mt][nt][2]; v1.y = acc[mt][nt][3];
            *(float2*)&C[(size_t)row * N + col] = v0;
            *(float2*)&C[(size_t)(row + 8) * N + col] = v1;
        }
    }
}

// ---------------- beta / g projections ----------------
#define BG_RG 4
__global__ __launch_bounds__(256) void bg_kernel(
    const float* __restrict__ hs, const float* __restrict__ W_b, const float* __restrict__ W_a,
    const float* __restrict__ dt_bias, const float* __restrict__ A_log,
    float* __restrict__ beta, float* __restrict__ gg)
{
    __shared__ float hsm[BG_RG * HIDN];
    __shared__ float red[4 * BG_RG * 64];
    int r0 = blockIdx.x * BG_RG;
    int t = threadIdx.x;
    for (int o = t; o < BG_RG * HIDN / 4; o += 256)
        ((float4*)hsm)[o] = ((const float4*)(hs + (size_t)r0 * HIDN))[o];
    __syncthreads();

    int out = t & 63, part = t >> 6;
    const float* Wp = (out < 32) ? (W_b + out) : (W_a + out - 32);
    float acc[BG_RG];
#pragma unroll
    for (int r = 0; r < BG_RG; r++) acc[r] = 0.f;
    int kbase = part * (HIDN / 4);
    for (int kk = 0; kk < HIDN / 4; kk++) {
        int k = kbase + kk;
        float w2 = Wp[(size_t)k * 32];
#pragma unroll
        for (int r = 0; r < BG_RG; r++) acc[r] += hsm[r * HIDN + k] * w2;
    }
#pragma unroll
    for (int r = 0; r < BG_RG; r++) red[(part * BG_RG + r) * 64 + out] = acc[r];
    __syncthreads();

    int rr = t >> 6, oo = t & 63;
    float s = red[(0*BG_RG+rr)*64+oo] + red[(1*BG_RG+rr)*64+oo]
            + red[(2*BG_RG+rr)*64+oo] + red[(3*BG_RG+rr)*64+oo];
    size_t row = (size_t)r0 + rr;
    if (oo < 32) {
        beta[row * 32 + oo] = 1.f / (1.f + expf(-s));
    } else {
        int h = oo - 32;
        float x = s + dt_bias[h];
        float sp = (x > 20.f) ? x : log1pf(expf(x));
        gg[row * 32 + h] = -expf(A_log[h]) * sp;
    }
}

// ---------------- conv1d(K=4 causal) + SiLU + split + l2norm(q,k) ----------------
__global__ __launch_bounds__(128) void conv_silu_kernel(
    const float* __restrict__ mixed, const float* __restrict__ conv_w,
    float* __restrict__ qn, float* __restrict__ kn, float* __restrict__ vout)
{
    int unit = blockIdx.x;
    int s = blockIdx.y;
    int b = blockIdx.z;
    int d = threadIdx.x;
    int base = (unit < 16) ? unit * 128
             : (unit < 32) ? KEYD + (unit - 16) * 128
             : 2 * KEYD + (unit - 32) * 128;
    int c = base + d;
    const float* mb = mixed + (size_t)b * SS * CONVD + c;
    float acc = 0.f;
#pragma unroll
    for (int j = 0; j < 4; j++) {
        int sp = s + j - 3;
        float x = (sp >= 0) ? mb[(size_t)sp * CONVD] : 0.f;
        acc += conv_w[(size_t)c * 4 + j] * x;
    }
    float xs = acc / (1.f + expf(-acc));

    if (unit < 32) {
        __shared__ float red[4];
        float ss = xs * xs;
#pragma unroll
        for (int off = 16; off > 0; off >>= 1) ss += __shfl_down_sync(0xffffffffu, ss, off);
        if ((d & 31) == 0) red[d >> 5] = ss;
        __syncthreads();
        float tot = red[0] + red[1] + red[2] + red[3];
        float scale = rsqrtf(tot + 1e-6f);
        if (unit < 16) {
            scale *= 0.08838834764831845f;
            qn[(((size_t)(b * HKN + unit)) * SS + s) * 128 + d] = xs * scale;
        } else {
            kn[(((size_t)(b * HKN + unit - 16)) * SS + s) * 128 + d] = xs * scale;
        }
    } else {
        vout[(((size_t)(b * HVN + unit - 32)) * SS + s) * 128 + d] = xs;
    }
}

// ---------------- chunked gated delta rule ----------------
#define DELTA_SMEM_BYTES ((16384+8320+8192+8192+4096+4096+256)*4)

__global__ __launch_bounds__(256, 1) void delta_kernel(
    const float* __restrict__ qn, const float* __restrict__ kn,
    const float* __restrict__ vv, const float* __restrict__ beta,
    const float* __restrict__ gg, float* __restrict__ core)
{
    extern __shared__ float sm[];
    float* st  = sm;
    float* KT  = st + 16384;
    float* Qs  = KT + 8320;
    float* Vs  = Qs + 8192;
    float* Wm  = Vs + 8192;
    float* Am  = Wm + 4096;
    float* gcs = Am + 4096;
    float* bet = gcs + 64;
    float* egs = bet + 64;
    float* edl = egs + 64;

    int t = threadIdx.x;
    int b = blockIdx.x >> 5, h = blockIdx.x & 31, hk = h >> 1;
    const float* qb = qn + (size_t)(b*HKN+hk)*SS*128;
    const float* kb = kn + (size_t)(b*HKN+hk)*SS*128;
    const float* vb = vv + (size_t)(b*HVN+h)*SS*128;
    const float* bp = beta + (size_t)b*SS*HVN + h;
    const float* gp = gg   + (size_t)b*SS*HVN + h;
    float* cb = core + (size_t)(b*HVN+h)*SS*128;

    for (int i = t; i < 16384; i += 256) st[i] = 0.f;
    __syncthreads();

    for (int ck = 0; ck < NCHK; ck++) {
        size_t srow = (size_t)ck * 64;
        const float* qr = qb + srow*128;
        const float* kr = kb + srow*128;
        const float* vr = vb + srow*128;
        for (int idx = t; idx < 8192; idx += 256) {
            Qs[idx] = qr[idx];
            Vs[idx] = vr[idx];
            int i = idx >> 7, d = idx & 127;
            KT[d*65 + i] = kr[idx];
        }
        if (t < 64) {
            bet[t] = bp[(srow + t)*HVN];
            edl[t] = gp[(srow + t)*HVN];
        }
        __syncthreads();
        if (t == 0) {
            float r = 0.f;
            for (int i = 0; i < 64; i++) { r += edl[i]; gcs[i] = r; }
        }
        __syncthreads();
        if (t < 64) {
            egs[t] = expf(gcs[t]);
            edl[t] = expf(gcs[63] - gcs[t]);
        }
        __syncthreads();

        {
            int r0 = (t >> 3) * 2, c0 = (t & 7) * 8;
            float wa[2][8], aa[2][8];
#pragma unroll
            for (int i = 0; i < 2; i++)
#pragma unroll
                for (int j = 0; j < 8; j++) { wa[i][j] = 0.f; aa[i][j] = 0.f; }
            for (int d = 0; d < 128; d++) {
                float k0 = KT[d*65 + r0], k1 = KT[d*65 + r0 + 1];
                float q0 = Qs[r0*128 + d], q1 = Qs[(r0+1)*128 + d];
                const float* kj = &KT[d*65 + c0];
#pragma unroll
                for (int j = 0; j < 8; j++) {
                    float kv = kj[j];
                    wa[0][j] += k0*kv; wa[1][j] += k1*kv;
                    aa[0][j] += q0*kv; aa[1][j] += q1*kv;
                }
            }
#pragma unroll
            for (int ii = 0; ii < 2; ii++) {
                int i = r0 + ii; float bi = bet[i], gi = gcs[i];
#pragma unroll
                for (int j = 0; j < 8; j++) {
                    int jc = c0 + j;
                    float wv = 0.f, av = 0.f;
                    if (jc <= i) {
                        float e = expf(gi - gcs[jc]);
                        av = e * aa[ii][j];
                        if (jc < i) wv = bi * e * wa[ii][j];
                    }
                    Wm[i*64 + jc] = wv;
                    Am[i*64 + jc] = av;
                }
            }
        }
        {
            int r0 = (t >> 4) * 4, c0 = (t & 15) * 8;
            float acc[4][8];
#pragma unroll
            for (int i = 0; i < 4; i++)
#pragma unroll
                for (int j = 0; j < 8; j++) acc[i][j] = 0.f;
            for (int d = 0; d < 128; d++) {
                float kv[4];
#pragma unroll
                for (int i = 0; i < 4; i++) kv[i] = KT[d*65 + r0 + i];
                float4 s0 = *(float4*)&st[d*128 + c0];
                float4 s1 = *(float4*)&st[d*128 + c0 + 4];
                float sv[8] = {s0.x,s0.y,s0.z,s0.w,s1.x,s1.y,s1.z,s1.w};
#pragma unroll
                for (int i = 0; i < 4; i++)
#pragma unroll
                    for (int j = 0; j < 8; j++) acc[i][j] += kv[i]*sv[j];
            }
#pragma unroll
            for (int i = 0; i < 4; i++) {
                int r = r0 + i; float bi = bet[r], e = egs[r];
#pragma unroll
                for (int j = 0; j < 8; j++) {
                    int c = c0 + j;
                    Vs[r*128 + c] = bi*(Vs[r*128 + c] - e*acc[i][j]);
                }
            }
        }
        __syncthreads();
        if (t < 128) {
            float x[64];
#pragma unroll
            for (int i = 0; i < 64; i++) {
                float a0 = Vs[i*128 + t], a1 = 0.f;
                int j = 0;
#pragma unroll
                for (; j + 2 <= i; j += 2) {
                    a0 -= Wm[i*64 + j]   * x[j];
                    a1 -= Wm[i*64 + j+1] * x[j+1];
                }
                if (j < i) a0 -= Wm[i*64 + j] * x[j];
                x[i] = a0 + a1;
            }
#pragma unroll
            for (int i = 0; i < 64; i++) Vs[i*128 + t] = x[i];
        }
        __syncthreads();
        {
            int r0 = (t >> 4) * 4, c0 = (t & 15) * 8;
            float o1[4][8], o2[4][8];
#pragma unroll
            for (int i = 0; i < 4; i++)
#pragma unroll
                for (int j = 0; j < 8; j++) { o1[i][j] = 0.f; o2[i][j] = 0.f; }
            for (int d = 0; d < 128; d++) {
                float qv[4];
#pragma unroll
                for (int i = 0; i < 4; i++) qv[i] = Qs[(r0+i)*128 + d];
                float4 s0 = *(float4*)&st[d*128 + c0];
                float4 s1 = *(float4*)&st[d*128 + c0 + 4];
                float sv[8] = {s0.x,s0.y,s0.z,s0.w,s1.x,s1.y,s1.z,s1.w};
#pragma unroll
                for (int i = 0; i < 4; i++)
#pragma unroll
                    for (int j = 0; j < 8; j++) o1[i][j] += qv[i]*sv[j];
            }
            for (int jj = 0; jj < 64; jj++) {
                float av[4];
#pragma unroll
                for (int i = 0; i < 4; i++) av[i] = Am[(r0+i)*64 + jj];
                float4 v0 = *(float4*)&Vs[jj*128 + c0];
                float4 v1 = *(float4*)&Vs[jj*128 + c0 + 4];
                float vw[8] = {v0.x,v0.y,v0.z,v0.w,v1.x,v1.y,v1.z,v1.w};
#pragma unroll
                for (int i = 0; i < 4; i++)
#pragma unroll
                    for (int j = 0; j < 8; j++) o2[i][j] += av[i]*vw[j];
            }
#pragma unroll
            for (int i = 0; i < 4; i++) {
                int r = r0 + i; float e = egs[r];
#pragma unroll
                for (int j = 0; j < 8; j += 4) {
                    float4 v;
                    v.x = e*o1[i][j]   + o2[i][j];
                    v.y = e*o1[i][j+1] + o2[i][j+1];
                    v.z = e*o1[i][j+2] + o2[i][j+2];
                    v.w = e*o1[i][j+3] + o2[i][j+3];
                    *(float4*)&cb[(srow + r)*128 + c0 + j] = v;
                }
            }
        }
        __syncthreads();
        {
            int d0 = (t >> 4) * 8, v0 = (t & 15) * 8;
            float acc[8][8];
#pragma unroll
            for (int i = 0; i < 8; i++)
#pragma unroll
                for (int j = 0; j < 8; j++) acc[i][j] = 0.f;
            for (int i = 0; i < 64; i++) {
                float el = edl[i];
                float kv[8];
#pragma unroll
                for (int x2 = 0; x2 < 8; x2++) kv[x2] = KT[(d0+x2)*65 + i] * el;
                float4 a = *(float4*)&Vs[i*128 + v0];
                float4 bq = *(float4*)&Vs[i*128 + v0 + 4];
                float vw[8] = {a.x,a.y,a.z,a.w,bq.x,bq.y,bq.z,bq.w};
#pragma unroll
                for (int x2 = 0; x2 < 8; x2++)
#pragma unroll
                    for (int y = 0; y < 8; y++) acc[x2][y] += kv[x2]*vw[y];
            }
            float egl = expf(gcs[63]);
#pragma unroll
            for (int x2 = 0; x2 < 8; x2++)
#pragma unroll
                for (int y = 0; y < 8; y += 4) {
                    float4 s = *(float4*)&st[(d0+x2)*128 + v0 + y];
                    s.x = s.x*egl + acc[x2][y];
                    s.y = s.y*egl + acc[x2][y+1];
                    s.z = s.z*egl + acc[x2][y+2];
                    s.w = s.w*egl + acc[x2][y+3];
                    *(float4*)&st[(d0+x2)*128 + v0 + y] = s;
                }
        }
        __syncthreads();
    }
}

// ---------------- gated RMSNorm + SiLU(z) gate ----------------
__global__ __launch_bounds__(128) void normgate_kernel(
    const float* __restrict__ core, const float* __restrict__ z,
    const float* __restrict__ norm_weight, float* __restrict__ act)
{
    int s = blockIdx.x, h = blockIdx.y, b = blockIdx.z;
    int d = threadIdx.x;
    __shared__ float red[4];
    size_t ci = ((size_t)(b*HVN + h)*SS + s)*128 + d;
    float v = core[ci];
    float ss = v*v;
#pragma unroll
    for (int off = 16; off > 0; off >>= 1) ss += __shfl_down_sync(0xffffffffu, ss, off);
    if ((d & 31) == 0) red[d >> 5] = ss;
    __syncthreads();
    float var = (red[0]+red[1]+red[2]+red[3]) * (1.f/128.f);
    float scale = rsqrtf(var + 1e-6f) * norm_weight[d];
    size_t zi = ((size_t)b*SS + s)*VALD + h*128 + d;
    float zv = z[zi];
    float gate = zv / (1.f + expf(-zv));
    act[zi] = v * scale * gate;
}

extern "C" void kernel_launch(void* const* d_in, const int* in_sizes, int n_in,
                              void* d_out, int out_size) {
    const float* hs     = (const float*)d_in[0];
    const float* W_qkv  = (const float*)d_in[1];
    const float* conv_w = (const float*)d_in[2];
    const float* W_z    = (const float*)d_in[3];
    const float* W_b    = (const float*)d_in[4];
    const float* W_a    = (const float*)d_in[5];
    const float* dt_b   = (const float*)d_in[6];
    const float* A_log  = (const float*)d_in[7];
    const float* normw  = (const float*)d_in[8];
    const float* W_out  = (const float*)d_in[9];
    float* out = (float*)d_out;

    float *mixed, *z, *qn, *kn, *v, *core, *beta, *gg;
    cudaGetSymbolAddress((void**)&mixed, g_mixed);
    cudaGetSymbolAddress((void**)&z,     g_z);
    cudaGetSymbolAddress((void**)&qn,    g_qn);
    cudaGetSymbolAddress((void**)&kn,    g_kn);
    cudaGetSymbolAddress((void**)&v,     g_v);
    cudaGetSymbolAddress((void**)&core,  g_core);
    cudaGetSymbolAddress((void**)&beta,  g_beta);
    cudaGetSymbolAddress((void**)&gg,    g_gg);

    __nv_bfloat16 *hs_hi, *hs_lo, *wqkv_hi, *wqkv_lo, *wz_hi, *wz_lo, *wout_hi, *wout_lo, *act_hi, *act_lo;
    cudaGetSymbolAddress((void**)&hs_hi,   g_hs_hi);
    cudaGetSymbolAddress((void**)&hs_lo,   g_hs_lo);
    cudaGetSymbolAddress((void**)&wqkv_hi, g_wqkv_hi);
    cudaGetSymbolAddress((void**)&wqkv_lo, g_wqkv_lo);
    cudaGetSymbolAddress((void**)&wz_hi,   g_wz_hi);
    cudaGetSymbolAddress((void**)&wz_lo,   g_wz_lo);
    cudaGetSymbolAddress((void**)&wout_hi, g_wout_hi);
    cudaGetSymbolAddress((void**)&wout_lo, g_wout_lo);
    cudaGetSymbolAddress((void**)&act_hi,  g_act_hi);
    cudaGetSymbolAddress((void**)&act_lo,  g_act_lo);

    cudaFuncSetAttribute(delta_kernel, cudaFuncAttributeMaxDynamicSharedMemorySize, DELTA_SMEM_BYTES);
    cudaFuncSetAttribute(hmma_gemm_kernel, cudaFuncAttributeMaxDynamicSharedMemorySize, GEMM_SMEM);

    // bf16 splits
    split_kernel<<<2048, 256>>>(hs, hs_hi, hs_lo, (size_t)MROWS*HIDN);
    tsplit_kernel<<<dim3(CONVD/32, HIDN/32), 256>>>(W_qkv, wqkv_hi, wqkv_lo, HIDN, CONVD);
    tsplit_kernel<<<dim3(VALD/32, HIDN/32), 256>>>(W_z, wz_hi, wz_lo, HIDN, VALD);
    tsplit_kernel<<<dim3(HIDN/32, VALD/32), 256>>>(W_out, wout_hi, wout_lo, VALD, HIDN);

    // 1) mixed = hs @ W_qkv
    hmma_gemm_kernel<<<dim3(MROWS/128, CONVD/128), 256, GEMM_SMEM>>>(
        hs_hi, hs_lo, wqkv_hi, wqkv_lo, mixed, MROWS, CONVD, HIDN);
    // 2) z = hs @ W_z
    hmma_gemm_kernel<<<dim3(MROWS/128, VALD/128), 256, GEMM_SMEM>>>(
        hs_hi, hs_lo, wz_hi, wz_lo, z, MROWS, VALD, HIDN);
    // 3) beta, g
    bg_kernel<<<MROWS/BG_RG, 256>>>(hs, W_b, W_a, dt_b, A_log, beta, gg);
    // 4) conv + silu + split + l2norm
    conv_silu_kernel<<<dim3(64, SS, BB), 128>>>(mixed, conv_w, qn, kn, v);
    // 5) chunked gated delta rule
    delta_kernel<<<BB*HVN, 256, DELTA_SMEM_BYTES>>>(qn, kn, v, beta, gg, core);
    // 6) gated rmsnorm * silu(z) -> act
    normgate_kernel<<<dim3(SS, HVN, BB), 128>>>(core, z, normw, mixed);
    // 7) out = act @ W_out
    split_kernel<<<2048, 256>>>(mixed, act_hi, act_lo, (size_t)MROWS*VALD);
    hmma_gemm_kernel<<<dim3(MROWS/128, HIDN/128), 256, GEMM_SMEM>>>(
        act_hi, act_lo, wout_hi, wout_lo, out, MROWS, HIDN, VALD);
}

// round 7
// speedup vs baseline: 2.0757x; 1.0892x over previous
#include <cuda_runtime.h>
#include <cuda_bf16.h>
#include <math.h>
#include <stdint.h>

#define BB    2
#define SS    4096
#define HIDN  2048
#define HVN   32
#define HKN   16
#define CONVD 8192
#define KEYD  2048
#define VALD  4096
#define NCHK  64
#define MROWS (BB*SS)

// ---------------- device scratch ----------------
__device__ float g_mixed[(size_t)BB*SS*CONVD];
__device__ float g_z    [(size_t)BB*SS*VALD];
__device__ float g_qn   [(size_t)BB*HKN*SS*128];
__device__ float g_kn   [(size_t)BB*HKN*SS*128];
__device__ float g_v    [(size_t)BB*HVN*SS*128];
__device__ float g_core [(size_t)BB*HVN*SS*128];
__device__ float g_beta [(size_t)BB*SS*HVN];
__device__ float g_gg   [(size_t)BB*SS*HVN];

__device__ __nv_bfloat16 g_hs_hi [(size_t)MROWS*HIDN];
__device__ __nv_bfloat16 g_hs_lo [(size_t)MROWS*HIDN];
__device__ __nv_bfloat16 g_wqkv_hi[(size_t)CONVD*HIDN];  // [N,K]
__device__ __nv_bfloat16 g_wqkv_lo[(size_t)CONVD*HIDN];
__device__ __nv_bfloat16 g_wz_hi  [(size_t)VALD*HIDN];
__device__ __nv_bfloat16 g_wz_lo  [(size_t)VALD*HIDN];
__device__ __nv_bfloat16 g_wout_hi[(size_t)HIDN*VALD];
__device__ __nv_bfloat16 g_wout_lo[(size_t)HIDN*VALD];
__device__ __nv_bfloat16 g_act_hi [(size_t)MROWS*VALD];
__device__ __nv_bfloat16 g_act_lo [(size_t)MROWS*VALD];

// ---------------- helpers ----------------
__device__ __forceinline__ uint32_t smem_u32(const void* p) {
    uint32_t a;
    asm("{ .reg .u64 t; cvta.to.shared.u64 t, %1; cvt.u32.u64 %0, t; }" : "=r"(a) : "l"(p));
    return a;
}
__device__ __forceinline__ void ldsm4(uint32_t* r, uint32_t addr) {
    asm volatile("ldmatrix.sync.aligned.m8n8.x4.shared.b16 {%0,%1,%2,%3}, [%4];"
        : "=r"(r[0]), "=r"(r[1]), "=r"(r[2]), "=r"(r[3]) : "r"(addr));
}
__device__ __forceinline__ void mma16816(float* c, const uint32_t* a, const uint32_t* b) {
    asm volatile("mma.sync.aligned.m16n8k16.row.col.f32.bf16.bf16.f32 "
        "{%0,%1,%2,%3}, {%4,%5,%6,%7}, {%8,%9}, {%0,%1,%2,%3};"
        : "+f"(c[0]), "+f"(c[1]), "+f"(c[2]), "+f"(c[3])
        : "r"(a[0]), "r"(a[1]), "r"(a[2]), "r"(a[3]), "r"(b[0]), "r"(b[1]));
}
__device__ __forceinline__ void cp16(uint32_t dst, const void* src) {
    asm volatile("cp.async.cg.shared.global [%0], [%1], 16;" :: "r"(dst), "l"(src));
}

// ---------------- split kernels ----------------
__global__ __launch_bounds__(256) void split_kernel(
    const float* __restrict__ in, __nv_bfloat16* __restrict__ hi, __nv_bfloat16* __restrict__ lo, size_t n)
{
    size_t i = (size_t)blockIdx.x * 256 + threadIdx.x;
    size_t stride = (size_t)gridDim.x * 256;
    for (; i < n; i += stride) {
        float v = in[i];
        __nv_bfloat16 h = __float2bfloat16_rn(v);
        hi[i] = h;
        lo[i] = __float2bfloat16_rn(v - __bfloat162float(h));
    }
}

// W[K,N] -> [N,K] hi/lo
__global__ __launch_bounds__(256) void tsplit_kernel(
    const float* __restrict__ W, __nv_bfloat16* __restrict__ Thi, __nv_bfloat16* __restrict__ Tlo,
    int K, int N)
{
    __shared__ float tile[32][33];
    int tx = threadIdx.x & 31, ty = threadIdx.x >> 5;
    int bx = blockIdx.x, by = blockIdx.y;
    for (int i = ty; i < 32; i += 8)
        tile[i][tx] = W[(size_t)(by*32 + i) * N + bx*32 + tx];
    __syncthreads();
    for (int i = ty; i < 32; i += 8) {
        float v = tile[tx][i];
        __nv_bfloat16 h = __float2bfloat16_rn(v);
        size_t oi = (size_t)(bx*32 + i) * K + by*32 + tx;
        Thi[oi] = h;
        Tlo[oi] = __float2bfloat16_rn(v - __bfloat162float(h));
    }
}

// ---------------- HMMA bf16x3 GEMM: C[M,N] = A @ B^T ----------------
#define GS_ROW   80
#define GS_ARR   (128*GS_ROW)
#define GS_STAGE (4*GS_ARR)
#define GEMM_SMEM (2*GS_STAGE)

__global__ __launch_bounds__(256, 2) void hmma_gemm_kernel(
    const __nv_bfloat16* __restrict__ Ahi, const __nv_bfloat16* __restrict__ Alo,
    const __nv_bfloat16* __restrict__ Bhi, const __nv_bfloat16* __restrict__ Blo,
    float* __restrict__ C, int M, int N, int K)
{
    extern __shared__ char smem[];
    uint32_t sb = smem_u32(smem);
    int t = threadIdx.x;
    int m0 = blockIdx.x * 128;
    int n0 = blockIdx.y * 128;
    int w = t >> 5, l = t & 31;
    int wm = w & 3, wn = w >> 2;

    const __nv_bfloat16* srcs[4] = { Ahi, Alo, Bhi, Blo };
    int rowbase[4];
    rowbase[0] = m0; rowbase[1] = m0; rowbase[2] = n0; rowbase[3] = n0;

    float acc[2][8][4];
#pragma unroll
    for (int i = 0; i < 2; i++)
#pragma unroll
        for (int j = 0; j < 8; j++)
#pragma unroll
            for (int r = 0; r < 4; r++) acc[i][j][r] = 0.f;

    int KT = K >> 5;

    auto load_stage = [&](int s, int k0) {
        uint32_t stb = sb + s * GS_STAGE;
#pragma unroll
        for (int c = 0; c < 8; c++) {
            int idx = t + c * 256;
            int arr = idx >> 9;
            int within = idx & 511;
            int row = within >> 2, ch = within & 3;
            const __nv_bfloat16* src = srcs[arr] + (size_t)(rowbase[arr] + row) * K + k0 + ch * 8;
            cp16(stb + arr * GS_ARR + row * GS_ROW + ch * 16, src);
        }
        asm volatile("cp.async.commit_group;");
    };

    load_stage(0, 0);

    int a_off = (wm * 32 + (l & 15)) * GS_ROW + ((l >> 4) * 16);
    int b_off = (wn * 64 + (l & 7) + ((l >> 4) << 3)) * GS_ROW + (((l >> 3) & 1) * 16);

    for (int kt = 0; kt < KT; kt++) {
        if (kt + 1 < KT) load_stage((kt + 1) & 1, (kt + 1) << 5);
        if (kt + 1 < KT) asm volatile("cp.async.wait_group 1;");
        else             asm volatile("cp.async.wait_group 0;");
        __syncthreads();

        uint32_t stb = sb + (kt & 1) * GS_STAGE;
#pragma unroll
        for (int ks = 0; ks < 2; ks++) {
            uint32_t ah[2][4], al[2][4];
#pragma unroll
            for (int mt = 0; mt < 2; mt++) {
                uint32_t aa = stb + a_off + mt * 16 * GS_ROW + ks * 32;
                ldsm4(ah[mt], aa);
                ldsm4(al[mt], aa + GS_ARR);
            }
#pragma unroll
            for (int ntp = 0; ntp < 4; ntp++) {
                uint32_t ba = stb + 2 * GS_ARR + b_off + ntp * 16 * GS_ROW + ks * 32;
                uint32_t bh[4], bl[4];
                ldsm4(bh, ba);
                ldsm4(bl, ba + GS_ARR);
#pragma unroll
                for (int mt = 0; mt < 2; mt++) {
                    mma16816(acc[mt][2*ntp],   ah[mt], bh);
                    mma16816(acc[mt][2*ntp],   ah[mt], bl);
                    mma16816(acc[mt][2*ntp],   al[mt], bh);
                    mma16816(acc[mt][2*ntp+1], ah[mt], bh + 2);
                    mma16816(acc[mt][2*ntp+1], ah[mt], bl + 2);
                    mma16816(acc[mt][2*ntp+1], al[mt], bh + 2);
                }
            }
        }
        __syncthreads();
    }

#pragma unroll
    for (int mt = 0; mt < 2; mt++) {
        int row = m0 + wm * 32 + mt * 16 + (l >> 2);
        int colb = n0 + wn * 64 + 2 * (l & 3);
#pragma unroll
        for (int nt = 0; nt < 8; nt++) {
            int col = colb + nt * 8;
            float2 v0; v0.x = acc[mt][nt][0]; v0.y = acc[mt][nt][1];
            float2 v1; v1.x = acc[mt][nt][2]; v1.y = acc[mt][nt][3];
            *(float2*)&C[(size_t)row * N + col] = v0;
            *(float2*)&C[(size_t)(row + 8) * N + col] = v1;
        }
    }
}

// ---------------- beta / g projections ----------------
#define BG_RG 4
__global__ __launch_bounds__(256) void bg_kernel(
    const float* __restrict__ hs, const float* __restrict__ W_b, const float* __restrict__ W_a,
    const float* __restrict__ dt_bias, const float* __restrict__ A_log,
    float* __restrict__ beta, float* __restrict__ gg)
{
    __shared__ float hsm[BG_RG * HIDN];
    __shared__ float red[4 * BG_RG * 64];
    int r0 = blockIdx.x * BG_RG;
    int t = threadIdx.x;
    for (int o = t; o < BG_RG * HIDN / 4; o += 256)
        ((float4*)hsm)[o] = ((const float4*)(hs + (size_t)r0 * HIDN))[o];
    __syncthreads();

    int out = t & 63, part = t >> 6;
    const float* Wp = (out < 32) ? (W_b + out) : (W_a + out - 32);
    float acc[BG_RG];
#pragma unroll
    for (int r = 0; r < BG_RG; r++) acc[r] = 0.f;
    int kbase = part * (HIDN / 4);
    for (int kk = 0; kk < HIDN / 4; kk++) {
        int k = kbase + kk;
        float w2 = Wp[(size_t)k * 32];
#pragma unroll
        for (int r = 0; r < BG_RG; r++) acc[r] += hsm[r * HIDN + k] * w2;
    }
#pragma unroll
    for (int r = 0; r < BG_RG; r++) red[(part * BG_RG + r) * 64 + out] = acc[r];
    __syncthreads();

    int rr = t >> 6, oo = t & 63;
    float s = red[(0*BG_RG+rr)*64+oo] + red[(1*BG_RG+rr)*64+oo]
            + red[(2*BG_RG+rr)*64+oo] + red[(3*BG_RG+rr)*64+oo];
    size_t row = (size_t)r0 + rr;
    if (oo < 32) {
        beta[row * 32 + oo] = 1.f / (1.f + expf(-s));
    } else {
        int h = oo - 32;
        float x = s + dt_bias[h];
        float sp = (x > 20.f) ? x : log1pf(expf(x));
        gg[row * 32 + h] = -expf(A_log[h]) * sp;
    }
}

// ---------------- conv1d(K=4 causal) + SiLU + split + l2norm(q,k) ----------------
__global__ __launch_bounds__(128) void conv_silu_kernel(
    const float* __restrict__ mixed, const float* __restrict__ conv_w,
    float* __restrict__ qn, float* __restrict__ kn, float* __restrict__ vout)
{
    int unit = blockIdx.x;
    int s = blockIdx.y;
    int b = blockIdx.z;
    int d = threadIdx.x;
    int base = (unit < 16) ? unit * 128
             : (unit < 32) ? KEYD + (unit - 16) * 128
             : 2 * KEYD + (unit - 32) * 128;
    int c = base + d;
    const float* mb = mixed + (size_t)b * SS * CONVD + c;
    float acc = 0.f;
#pragma unroll
    for (int j = 0; j < 4; j++) {
        int sp = s + j - 3;
        float x = (sp >= 0) ? mb[(size_t)sp * CONVD] : 0.f;
        acc += conv_w[(size_t)c * 4 + j] * x;
    }
    float xs = acc / (1.f + expf(-acc));

    if (unit < 32) {
        __shared__ float red[4];
        float ss = xs * xs;
#pragma unroll
        for (int off = 16; off > 0; off >>= 1) ss += __shfl_down_sync(0xffffffffu, ss, off);
        if ((d & 31) == 0) red[d >> 5] = ss;
        __syncthreads();
        float tot = red[0] + red[1] + red[2] + red[3];
        float scale = rsqrtf(tot + 1e-6f);
        if (unit < 16) {
            scale *= 0.08838834764831845f;
            qn[(((size_t)(b * HKN + unit)) * SS + s) * 128 + d] = xs * scale;
        } else {
            kn[(((size_t)(b * HKN + unit - 16)) * SS + s) * 128 + d] = xs * scale;
        }
    } else {
        vout[(((size_t)(b * HVN + unit - 32)) * SS + s) * 128 + d] = xs;
    }
}

// ---------------- chunked gated delta rule, DV split x2 ----------------
// grid = BB*HVN*2 blocks; block handles (b, h, 64-wide value slice).
// smem floats: st 128*64=8192 | KT 128*65=8320 | Qs 64*128=8192 | Vs 64*64=4096
//            | Wm 4096 | Am 4096 | scalars 256
#define DELTA_SMEM_BYTES ((8192+8320+8192+4096+4096+4096+256)*4)

__global__ __launch_bounds__(256, 1) void delta_kernel(
    const float* __restrict__ qn, const float* __restrict__ kn,
    const float* __restrict__ vv, const float* __restrict__ beta,
    const float* __restrict__ gg, float* __restrict__ core)
{
    extern __shared__ float sm[];
    float* st  = sm;          // [128][64]
    float* KT  = st + 8192;   // [128][65]
    float* Qs  = KT + 8320;   // [64][128]
    float* Vs  = Qs + 8192;   // [64][64]
    float* Wm  = Vs + 4096;   // [64][64]
    float* Am  = Wm + 4096;   // [64][64]
    float* gcs = Am + 4096;
    float* bet = gcs + 64;
    float* egs = bet + 64;
    float* edl = egs + 64;

    int t = threadIdx.x;
    int vs = blockIdx.x & 1;            // value slice
    int h  = (blockIdx.x >> 1) & 31;
    int b  = blockIdx.x >> 6;
    int vo = vs * 64;
    int hk = h >> 1;
    const float* qb = qn + (size_t)(b*HKN+hk)*SS*128;
    const float* kb = kn + (size_t)(b*HKN+hk)*SS*128;
    const float* vb = vv + (size_t)(b*HVN+h)*SS*128;
    const float* bp = beta + (size_t)b*SS*HVN + h;
    const float* gp = gg   + (size_t)b*SS*HVN + h;
    float* cb = core + (size_t)(b*HVN+h)*SS*128;

    for (int i = t; i < 8192; i += 256) st[i] = 0.f;
    __syncthreads();

    for (int ck = 0; ck < NCHK; ck++) {
        size_t srow = (size_t)ck * 64;
        const float* qr = qb + srow*128;
        const float* kr = kb + srow*128;
        const float* vr = vb + srow*128;
        for (int idx = t; idx < 8192; idx += 256) {
            Qs[idx] = qr[idx];
            int i = idx >> 7, d = idx & 127;
            KT[d*65 + i] = kr[idx];
        }
        for (int idx = t; idx < 4096; idx += 256) {
            int i = idx >> 6, c = idx & 63;
            Vs[idx] = vr[i*128 + vo + c];
        }
        if (t < 64) {
            bet[t] = bp[(srow + t)*HVN];
            edl[t] = gp[(srow + t)*HVN];
        }
        __syncthreads();
        if (t == 0) {
            float r = 0.f;
            for (int i = 0; i < 64; i++) { r += edl[i]; gcs[i] = r; }
        }
        __syncthreads();
        if (t < 64) {
            egs[t] = expf(gcs[t]);
            edl[t] = expf(gcs[63] - gcs[t]);
        }
        __syncthreads();

        // ---- W (strict lower, beta*kk*decay) and A (lower, qk*decay) ----
        {
            int r0 = (t >> 3) * 2, c0 = (t & 7) * 8;
            float wa[2][8], aa[2][8];
#pragma unroll
            for (int i = 0; i < 2; i++)
#pragma unroll
                for (int j = 0; j < 8; j++) { wa[i][j] = 0.f; aa[i][j] = 0.f; }
            for (int d = 0; d < 128; d++) {
                float k0 = KT[d*65 + r0], k1 = KT[d*65 + r0 + 1];
                float q0 = Qs[r0*128 + d], q1 = Qs[(r0+1)*128 + d];
                const float* kj = &KT[d*65 + c0];
#pragma unroll
                for (int j = 0; j < 8; j++) {
                    float kv = kj[j];
                    wa[0][j] += k0*kv; wa[1][j] += k1*kv;
                    aa[0][j] += q0*kv; aa[1][j] += q1*kv;
                }
            }
#pragma unroll
            for (int ii = 0; ii < 2; ii++) {
                int i = r0 + ii; float bi = bet[i], gi = gcs[i];
#pragma unroll
                for (int j = 0; j < 8; j++) {
                    int jc = c0 + j;
                    float wv = 0.f, av = 0.f;
                    if (jc <= i) {
                        float e = expf(gi - gcs[jc]);
                        av = e * aa[ii][j];
                        if (jc < i) wv = bi * e * wa[ii][j];
                    }
                    Wm[i*64 + jc] = wv;
                    Am[i*64 + jc] = av;
                }
            }
        }
        // ---- X = beta*(v - e^{gc} * (k @ st))  (overwrite Vs, [64][64]) ----
        {
            int r0 = (t >> 3) * 2, c0 = (t & 7) * 8;
            float acc[2][8];
#pragma unroll
            for (int i = 0; i < 2; i++)
#pragma unroll
                for (int j = 0; j < 8; j++) acc[i][j] = 0.f;
            for (int d = 0; d < 128; d++) {
                float kv0 = KT[d*65 + r0], kv1 = KT[d*65 + r0 + 1];
                float4 s0 = *(float4*)&st[d*64 + c0];
                float4 s1 = *(float4*)&st[d*64 + c0 + 4];
                float sv[8] = {s0.x,s0.y,s0.z,s0.w,s1.x,s1.y,s1.z,s1.w};
#pragma unroll
                for (int j = 0; j < 8; j++) {
                    acc[0][j] += kv0*sv[j];
                    acc[1][j] += kv1*sv[j];
                }
            }
            __syncthreads();
#pragma unroll
            for (int i = 0; i < 2; i++) {
                int r = r0 + i; float bi = bet[r], e = egs[r];
#pragma unroll
                for (int j = 0; j < 8; j++) {
                    int c = c0 + j;
                    Vs[r*64 + c] = bi*(Vs[r*64 + c] - e*acc[i][j]);
                }
            }
        }
        __syncthreads();
        // ---- forward substitution: v_new = (I+W)^{-1} X, 64 columns ----
        if (t < 64) {
            float x[64];
#pragma unroll
            for (int i = 0; i < 64; i++) {
                float a0 = Vs[i*64 + t], a1 = 0.f;
                int j = 0;
#pragma unroll
                for (; j + 2 <= i; j += 2) {
                    a0 -= Wm[i*64 + j]   * x[j];
                    a1 -= Wm[i*64 + j+1] * x[j+1];
                }
                if (j < i) a0 -= Wm[i*64 + j] * x[j];
                x[i] = a0 + a1;
            }
#pragma unroll
            for (int i = 0; i < 64; i++) Vs[i*64 + t] = x[i];
        }
        __syncthreads();
        // ---- out = e^{gc} * (q @ st) + Am @ v_new  ([64][64] slice) ----
        {
            int r0 = (t >> 3) * 2, c0 = (t & 7) * 8;
            float o1[2][8], o2[2][8];
#pragma unroll
            for (int i = 0; i < 2; i++)
#pragma unroll
                for (int j = 0; j < 8; j++) { o1[i][j] = 0.f; o2[i][j] = 0.f; }
            for (int d = 0; d < 128; d++) {
                float q0 = Qs[r0*128 + d], q1 = Qs[(r0+1)*128 + d];
                float4 s0 = *(float4*)&st[d*64 + c0];
                float4 s1 = *(float4*)&st[d*64 + c0 + 4];
                float sv[8] = {s0.x,s0.y,s0.z,s0.w,s1.x,s1.y,s1.z,s1.w};
#pragma unroll
                for (int j = 0; j < 8; j++) {
                    o1[0][j] += q0*sv[j];
                    o1[1][j] += q1*sv[j];
                }
            }
            for (int jj = 0; jj < 64; jj++) {
                float a0 = Am[r0*64 + jj], a1 = Am[(r0+1)*64 + jj];
                float4 v0 = *(float4*)&Vs[jj*64 + c0];
                float4 v1 = *(float4*)&Vs[jj*64 + c0 + 4];
                float vw[8] = {v0.x,v0.y,v0.z,v0.w,v1.x,v1.y,v1.z,v1.w};
#pragma unroll
                for (int j = 0; j < 8; j++) {
                    o2[0][j] += a0*vw[j];
                    o2[1][j] += a1*vw[j];
                }
            }
#pragma unroll
            for (int i = 0; i < 2; i++) {
                int r = r0 + i; float e = egs[r];
#pragma unroll
                for (int j = 0; j < 8; j += 4) {
                    float4 v;
                    v.x = e*o1[i][j]   + o2[i][j];
                    v.y = e*o1[i][j+1] + o2[i][j+1];
                    v.z = e*o1[i][j+2] + o2[i][j+2];
                    v.w = e*o1[i][j+3] + o2[i][j+3];
                    *(float4*)&cb[(srow + r)*128 + vo + c0 + j] = v;
                }
            }
        }
        __syncthreads();
        // ---- state update: st = st*e^{gl} + (k*edl)^T @ v_new  [128][64] ----
        {
            int d0 = (t >> 3) * 4, v0 = (t & 7) * 8;
            float acc[4][8];
#pragma unroll
            for (int i = 0; i < 4; i++)
#pragma unroll
                for (int j = 0; j < 8; j++) acc[i][j] = 0.f;
            for (int i = 0; i < 64; i++) {
                float el = edl[i];
                float kv[4];
#pragma unroll
                for (int x2 = 0; x2 < 4; x2++) kv[x2] = KT[(d0+x2)*65 + i] * el;
                float4 a = *(float4*)&Vs[i*64 + v0];
                float4 bq = *(float4*)&Vs[i*64 + v0 + 4];
                float vw[8] = {a.x,a.y,a.z,a.w,bq.x,bq.y,bq.z,bq.w};
#pragma unroll
                for (int x2 = 0; x2 < 4; x2++)
#pragma unroll
                    for (int y = 0; y < 8; y++) acc[x2][y] += kv[x2]*vw[y];
            }
            float egl = expf(gcs[63]);
#pragma unroll
            for (int x2 = 0; x2 < 4; x2++)
#pragma unroll
                for (int y = 0; y < 8; y += 4) {
                    float4 s = *(float4*)&st[(d0+x2)*64 + v0 + y];
                    s.x = s.x*egl + acc[x2][y];
                    s.y = s.y*egl + acc[x2][y+1];
                    s.z = s.z*egl + acc[x2][y+2];
                    s.w = s.w*egl + acc[x2][y+3];
                    *(float4*)&st[(d0+x2)*64 + v0 + y] = s;
                }
        }
        __syncthreads();
    }
}

// ---------------- gated RMSNorm + SiLU(z) gate -> bf16 hi/lo for final GEMM ----------------
__global__ __launch_bounds__(128) void normgate_kernel(
    const float* __restrict__ core, const float* __restrict__ z,
    const float* __restrict__ norm_weight,
    __nv_bfloat16* __restrict__ act_hi, __nv_bfloat16* __restrict__ act_lo)
{
    int s = blockIdx.x, h = blockIdx.y, b = blockIdx.z;
    int d = threadIdx.x;
    __shared__ float red[4];
    size_t ci = ((size_t)(b*HVN + h)*SS + s)*128 + d;
    float v = core[ci];
    float ss = v*v;
#pragma unroll
    for (int off = 16; off > 0; off >>= 1) ss += __shfl_down_sync(0xffffffffu, ss, off);
    if ((d & 31) == 0) red[d >> 5] = ss;
    __syncthreads();
    float var = (red[0]+red[1]+red[2]+red[3]) * (1.f/128.f);
    float scale = rsqrtf(var + 1e-6f) * norm_weight[d];
    size_t zi = ((size_t)b*SS + s)*VALD + h*128 + d;
    float zv = z[zi];
    float gate = zv / (1.f + expf(-zv));
    float val = v * scale * gate;
    __nv_bfloat16 hv = __float2bfloat16_rn(val);
    act_hi[zi] = hv;
    act_lo[zi] = __float2bfloat16_rn(val - __bfloat162float(hv));
}

extern "C" void kernel_launch(void* const* d_in, const int* in_sizes, int n_in,
                              void* d_out, int out_size) {
    const float* hs     = (const float*)d_in[0];
    const float* W_qkv  = (const float*)d_in[1];
    const float* conv_w = (const float*)d_in[2];
    const float* W_z    = (const float*)d_in[3];
    const float* W_b    = (const float*)d_in[4];
    const float* W_a    = (const float*)d_in[5];
    const float* dt_b   = (const float*)d_in[6];
    const float* A_log  = (const float*)d_in[7];
    const float* normw  = (const float*)d_in[8];
    const float* W_out  = (const float*)d_in[9];
    float* out = (float*)d_out;

    float *mixed, *z, *qn, *kn, *v, *core, *beta, *gg;
    cudaGetSymbolAddress((void**)&mixed, g_mixed);
    cudaGetSymbolAddress((void**)&z,     g_z);
    cudaGetSymbolAddress((void**)&qn,    g_qn);
    cudaGetSymbolAddress((void**)&kn,    g_kn);
    cudaGetSymbolAddress((void**)&v,     g_v);
    cudaGetSymbolAddress((void**)&core,  g_core);
    cudaGetSymbolAddress((void**)&beta,  g_beta);
    cudaGetSymbolAddress((void**)&gg,    g_gg);

    __nv_bfloat16 *hs_hi, *hs_lo, *wqkv_hi, *wqkv_lo, *wz_hi, *wz_lo, *wout_hi, *wout_lo, *act_hi, *act_lo;
    cudaGetSymbolAddress((void**)&hs_hi,   g_hs_hi);
    cudaGetSymbolAddress((void**)&hs_lo,   g_hs_lo);
    cudaGetSymbolAddress((void**)&wqkv_hi, g_wqkv_hi);
    cudaGetSymbolAddress((void**)&wqkv_lo, g_wqkv_lo);
    cudaGetSymbolAddress((void**)&wz_hi,   g_wz_hi);
    cudaGetSymbolAddress((void**)&wz_lo,   g_wz_lo);
    cudaGetSymbolAddress((void**)&wout_hi, g_wout_hi);
    cudaGetSymbolAddress((void**)&wout_lo, g_wout_lo);
    cudaGetSymbolAddress((void**)&act_hi,  g_act_hi);
    cudaGetSymbolAddress((void**)&act_lo,  g_act_lo);

    cudaFuncSetAttribute(delta_kernel, cudaFuncAttributeMaxDynamicSharedMemorySize, DELTA_SMEM_BYTES);
    cudaFuncSetAttribute(hmma_gemm_kernel, cudaFuncAttributeMaxDynamicSharedMemorySize, GEMM_SMEM);

    // bf16 splits
    split_kernel<<<2048, 256>>>(hs, hs_hi, hs_lo, (size_t)MROWS*HIDN);
    tsplit_kernel<<<dim3(CONVD/32, HIDN/32), 256>>>(W_qkv, wqkv_hi, wqkv_lo, HIDN, CONVD);
    tsplit_kernel<<<dim3(VALD/32, HIDN/32), 256>>>(W_z, wz_hi, wz_lo, HIDN, VALD);
    tsplit_kernel<<<dim3(HIDN/32, VALD/32), 256>>>(W_out, wout_hi, wout_lo, VALD, HIDN);

    // 1) mixed = hs @ W_qkv
    hmma_gemm_kernel<<<dim3(MROWS/128, CONVD/128), 256, GEMM_SMEM>>>(
        hs_hi, hs_lo, wqkv_hi, wqkv_lo, mixed, MROWS, CONVD, HIDN);
    // 2) z = hs @ W_z
    hmma_gemm_kernel<<<dim3(MROWS/128, VALD/128), 256, GEMM_SMEM>>>(
        hs_hi, hs_lo, wz_hi, wz_lo, z, MROWS, VALD, HIDN);
    // 3) beta, g
    bg_kernel<<<MROWS/BG_RG, 256>>>(hs, W_b, W_a, dt_b, A_log, beta, gg);
    // 4) conv + silu + split + l2norm
    conv_silu_kernel<<<dim3(64, SS, BB), 128>>>(mixed, conv_w, qn, kn, v);
    // 5) chunked gated delta rule (DV split x2 -> 128 blocks)
    delta_kernel<<<BB*HVN*2, 256, DELTA_SMEM_BYTES>>>(qn, kn, v, beta, gg, core);
    // 6) gated rmsnorm * silu(z) -> act hi/lo (fused split)
    normgate_kernel<<<dim3(SS, HVN, BB), 128>>>(core, z, normw, act_hi, act_lo);
    // 7) out = act @ W_out
    hmma_gemm_kernel<<<dim3(MROWS/128, HIDN/128), 256, GEMM_SMEM>>>(
        act_hi, act_lo, wout_hi, wout_lo, out, MROWS, HIDN, VALD);
}

// round 8
// speedup vs baseline: 2.0833x; 1.0037x over previous
#include <cuda_runtime.h>
#include <cuda_bf16.h>
#include <math.h>
#include <stdint.h>

#define BB    2
#define SS    4096
#define HIDN  2048
#define HVN   32
#define HKN   16
#define CONVD 8192
#define KEYD  2048
#define VALD  4096
#define NCHK  64
#define MROWS (BB*SS)

// ---------------- device scratch ----------------
__device__ float g_mixed[(size_t)BB*SS*CONVD];
__device__ float g_z    [(size_t)BB*SS*VALD];
__device__ float g_qn   [(size_t)BB*HKN*SS*128];
__device__ float g_kn   [(size_t)BB*HKN*SS*128];
__device__ float g_v    [(size_t)BB*HVN*SS*128];
__device__ float g_core [(size_t)BB*HVN*SS*128];
__device__ float g_beta [(size_t)BB*SS*HVN];
__device__ float g_gg   [(size_t)BB*SS*HVN];

__device__ __nv_bfloat16 g_hs_hi [(size_t)MROWS*HIDN];
__device__ __nv_bfloat16 g_hs_lo [(size_t)MROWS*HIDN];
__device__ __nv_bfloat16 g_wqkv_hi[(size_t)CONVD*HIDN];  // [N,K]
__device__ __nv_bfloat16 g_wqkv_lo[(size_t)CONVD*HIDN];
__device__ __nv_bfloat16 g_wz_hi  [(size_t)VALD*HIDN];
__device__ __nv_bfloat16 g_wz_lo  [(size_t)VALD*HIDN];
__device__ __nv_bfloat16 g_wout_hi[(size_t)HIDN*VALD];
__device__ __nv_bfloat16 g_wout_lo[(size_t)HIDN*VALD];
__device__ __nv_bfloat16 g_act_hi [(size_t)MROWS*VALD];
__device__ __nv_bfloat16 g_act_lo [(size_t)MROWS*VALD];

// ---------------- helpers ----------------
__device__ __forceinline__ uint32_t smem_u32(const void* p) {
    uint32_t a;
    asm("{ .reg .u64 t; cvta.to.shared.u64 t, %1; cvt.u32.u64 %0, t; }" : "=r"(a) : "l"(p));
    return a;
}
__device__ __forceinline__ void ldsm4(uint32_t* r, uint32_t addr) {
    asm volatile("ldmatrix.sync.aligned.m8n8.x4.shared.b16 {%0,%1,%2,%3}, [%4];"
        : "=r"(r[0]), "=r"(r[1]), "=r"(r[2]), "=r"(r[3]) : "r"(addr));
}
__device__ __forceinline__ void mma16816(float* c, const uint32_t* a, const uint32_t* b) {
    asm volatile("mma.sync.aligned.m16n8k16.row.col.f32.bf16.bf16.f32 "
        "{%0,%1,%2,%3}, {%4,%5,%6,%7}, {%8,%9}, {%0,%1,%2,%3};"
        : "+f"(c[0]), "+f"(c[1]), "+f"(c[2]), "+f"(c[3])
        : "r"(a[0]), "r"(a[1]), "r"(a[2]), "r"(a[3]), "r"(b[0]), "r"(b[1]));
}
__device__ __forceinline__ void cp16(uint32_t dst, const void* src) {
    asm volatile("cp.async.cg.shared.global [%0], [%1], 16;" :: "r"(dst), "l"(src));
}

// ---------------- split kernels ----------------
__global__ __launch_bounds__(256) void split_kernel(
    const float* __restrict__ in, __nv_bfloat16* __restrict__ hi, __nv_bfloat16* __restrict__ lo, size_t n)
{
    size_t i = (size_t)blockIdx.x * 256 + threadIdx.x;
    size_t stride = (size_t)gridDim.x * 256;
    for (; i < n; i += stride) {
        float v = in[i];
        __nv_bfloat16 h = __float2bfloat16_rn(v);
        hi[i] = h;
        lo[i] = __float2bfloat16_rn(v - __bfloat162float(h));
    }
}

// all three weights: W[K,N] -> [N,K] hi/lo, one launch
__global__ __launch_bounds__(256) void tsplit_all_kernel(
    const float* __restrict__ Wq, __nv_bfloat16* __restrict__ qh, __nv_bfloat16* __restrict__ ql,
    const float* __restrict__ Wz, __nv_bfloat16* __restrict__ zh, __nv_bfloat16* __restrict__ zl,
    const float* __restrict__ Wo, __nv_bfloat16* __restrict__ oh, __nv_bfloat16* __restrict__ ol)
{
    __shared__ float tile[32][33];
    int n = blockIdx.x;
    const float* W; __nv_bfloat16 *Thi, *Tlo; int K, N, bx, by;
    if (n < 16384)      { W = Wq; Thi = qh; Tlo = ql; K = HIDN; N = CONVD; bx = n & 255; by = n >> 8; }
    else if (n < 24576) { n -= 16384; W = Wz; Thi = zh; Tlo = zl; K = HIDN; N = VALD; bx = n & 127; by = n >> 7; }
    else                { n -= 24576; W = Wo; Thi = oh; Tlo = ol; K = VALD; N = HIDN; bx = n & 63;  by = n >> 6; }
    int tx = threadIdx.x & 31, ty = threadIdx.x >> 5;
    for (int i = ty; i < 32; i += 8)
        tile[i][tx] = W[(size_t)(by*32 + i) * N + bx*32 + tx];
    __syncthreads();
    for (int i = ty; i < 32; i += 8) {
        float v = tile[tx][i];
        __nv_bfloat16 h = __float2bfloat16_rn(v);
        size_t oi = (size_t)(bx*32 + i) * K + by*32 + tx;
        Thi[oi] = h;
        Tlo[oi] = __float2bfloat16_rn(v - __bfloat162float(h));
    }
}

// ---------------- HMMA bf16x3 GEMM: C[M,N] = A @ B^T ----------------
#define GS_ROW   80
#define GS_ARR   (128*GS_ROW)
#define GS_STAGE (4*GS_ARR)
#define GEMM_SMEM (2*GS_STAGE)

__global__ __launch_bounds__(256, 2) void hmma_gemm_kernel(
    const __nv_bfloat16* __restrict__ Ahi, const __nv_bfloat16* __restrict__ Alo,
    const __nv_bfloat16* __restrict__ Bhi, const __nv_bfloat16* __restrict__ Blo,
    float* __restrict__ C, int M, int N, int K)
{
    extern __shared__ char smem[];
    uint32_t sb = smem_u32(smem);
    int t = threadIdx.x;
    int m0 = blockIdx.x * 128;
    int n0 = blockIdx.y * 128;
    int w = t >> 5, l = t & 31;
    int wm = w & 3, wn = w >> 2;

    const __nv_bfloat16* srcs[4] = { Ahi, Alo, Bhi, Blo };
    int rowbase[4];
    rowbase[0] = m0; rowbase[1] = m0; rowbase[2] = n0; rowbase[3] = n0;

    float acc[2][8][4];
#pragma unroll
    for (int i = 0; i < 2; i++)
#pragma unroll
        for (int j = 0; j < 8; j++)
#pragma unroll
            for (int r = 0; r < 4; r++) acc[i][j][r] = 0.f;

    int KT = K >> 5;

    auto load_stage = [&](int s, int k0) {
        uint32_t stb = sb + s * GS_STAGE;
#pragma unroll
        for (int c = 0; c < 8; c++) {
            int idx = t + c * 256;
            int arr = idx >> 9;
            int within = idx & 511;
            int row = within >> 2, ch = within & 3;
            const __nv_bfloat16* src = srcs[arr] + (size_t)(rowbase[arr] + row) * K + k0 + ch * 8;
            cp16(stb + arr * GS_ARR + row * GS_ROW + ch * 16, src);
        }
        asm volatile("cp.async.commit_group;");
    };

    load_stage(0, 0);

    int a_off = (wm * 32 + (l & 15)) * GS_ROW + ((l >> 4) * 16);
    int b_off = (wn * 64 + (l & 7) + ((l >> 4) << 3)) * GS_ROW + (((l >> 3) & 1) * 16);

    for (int kt = 0; kt < KT; kt++) {
        if (kt + 1 < KT) load_stage((kt + 1) & 1, (kt + 1) << 5);
        if (kt + 1 < KT) asm volatile("cp.async.wait_group 1;");
        else             asm volatile("cp.async.wait_group 0;");
        __syncthreads();

        uint32_t stb = sb + (kt & 1) * GS_STAGE;
#pragma unroll
        for (int ks = 0; ks < 2; ks++) {
            uint32_t ah[2][4], al[2][4];
#pragma unroll
            for (int mt = 0; mt < 2; mt++) {
                uint32_t aa = stb + a_off + mt * 16 * GS_ROW + ks * 32;
                ldsm4(ah[mt], aa);
                ldsm4(al[mt], aa + GS_ARR);
            }
#pragma unroll
            for (int ntp = 0; ntp < 4; ntp++) {
                uint32_t ba = stb + 2 * GS_ARR + b_off + ntp * 16 * GS_ROW + ks * 32;
                uint32_t bh[4], bl[4];
                ldsm4(bh, ba);
                ldsm4(bl, ba + GS_ARR);
#pragma unroll
                for (int mt = 0; mt < 2; mt++) {
                    mma16816(acc[mt][2*ntp],   ah[mt], bh);
                    mma16816(acc[mt][2*ntp],   ah[mt], bl);
                    mma16816(acc[mt][2*ntp],   al[mt], bh);
                    mma16816(acc[mt][2*ntp+1], ah[mt], bh + 2);
                    mma16816(acc[mt][2*ntp+1], ah[mt], bl + 2);
                    mma16816(acc[mt][2*ntp+1], al[mt], bh + 2);
                }
            }
        }
        __syncthreads();
    }

#pragma unroll
    for (int mt = 0; mt < 2; mt++) {
        int row = m0 + wm * 32 + mt * 16 + (l >> 2);
        int colb = n0 + wn * 64 + 2 * (l & 3);
#pragma unroll
        for (int nt = 0; nt < 8; nt++) {
            int col = colb + nt * 8;
            float2 v0; v0.x = acc[mt][nt][0]; v0.y = acc[mt][nt][1];
            float2 v1; v1.x = acc[mt][nt][2]; v1.y = acc[mt][nt][3];
            *(float2*)&C[(size_t)row * N + col] = v0;
            *(float2*)&C[(size_t)(row + 8) * N + col] = v1;
        }
    }
}

// ---------------- beta / g projections ----------------
#define BG_RG 4
__global__ __launch_bounds__(256) void bg_kernel(
    const float* __restrict__ hs, const float* __restrict__ W_b, const float* __restrict__ W_a,
    const float* __restrict__ dt_bias, const float* __restrict__ A_log,
    float* __restrict__ beta, float* __restrict__ gg)
{
    __shared__ float hsm[BG_RG * HIDN];
    __shared__ float red[4 * BG_RG * 64];
    int r0 = blockIdx.x * BG_RG;
    int t = threadIdx.x;
    for (int o = t; o < BG_RG * HIDN / 4; o += 256)
        ((float4*)hsm)[o] = ((const float4*)(hs + (size_t)r0 * HIDN))[o];
    __syncthreads();

    int out = t & 63, part = t >> 6;
    const float* Wp = (out < 32) ? (W_b + out) : (W_a + out - 32);
    float acc[BG_RG];
#pragma unroll
    for (int r = 0; r < BG_RG; r++) acc[r] = 0.f;
    int kbase = part * (HIDN / 4);
    for (int kk = 0; kk < HIDN / 4; kk++) {
        int k = kbase + kk;
        float w2 = Wp[(size_t)k * 32];
#pragma unroll
        for (int r = 0; r < BG_RG; r++) acc[r] += hsm[r * HIDN + k] * w2;
    }
#pragma unroll
    for (int r = 0; r < BG_RG; r++) red[(part * BG_RG + r) * 64 + out] = acc[r];
    __syncthreads();

    int rr = t >> 6, oo = t & 63;
    float s = red[(0*BG_RG+rr)*64+oo] + red[(1*BG_RG+rr)*64+oo]
            + red[(2*BG_RG+rr)*64+oo] + red[(3*BG_RG+rr)*64+oo];
    size_t row = (size_t)r0 + rr;
    if (oo < 32) {
        beta[row * 32 + oo] = 1.f / (1.f + expf(-s));
    } else {
        int h = oo - 32;
        float x = s + dt_bias[h];
        float sp = (x > 20.f) ? x : log1pf(expf(x));
        gg[row * 32 + h] = -expf(A_log[h]) * sp;
    }
}

// ---------------- conv1d(K=4 causal) + SiLU + split + l2norm(q,k) ----------------
__global__ __launch_bounds__(128) void conv_silu_kernel(
    const float* __restrict__ mixed, const float* __restrict__ conv_w,
    float* __restrict__ qn, float* __restrict__ kn, float* __restrict__ vout)
{
    int unit = blockIdx.x;
    int s = blockIdx.y;
    int b = blockIdx.z;
    int d = threadIdx.x;
    int base = (unit < 16) ? unit * 128
             : (unit < 32) ? KEYD + (unit - 16) * 128
             : 2 * KEYD + (unit - 32) * 128;
    int c = base + d;
    const float* mb = mixed + (size_t)b * SS * CONVD + c;
    float acc = 0.f;
#pragma unroll
    for (int j = 0; j < 4; j++) {
        int sp = s + j - 3;
        float x = (sp >= 0) ? mb[(size_t)sp * CONVD] : 0.f;
        acc += conv_w[(size_t)c * 4 + j] * x;
    }
    float xs = acc / (1.f + expf(-acc));

    if (unit < 32) {
        __shared__ float red[4];
        float ss = xs * xs;
#pragma unroll
        for (int off = 16; off > 0; off >>= 1) ss += __shfl_down_sync(0xffffffffu, ss, off);
        if ((d & 31) == 0) red[d >> 5] = ss;
        __syncthreads();
        float tot = red[0] + red[1] + red[2] + red[3];
        float scale = rsqrtf(tot + 1e-6f);
        if (unit < 16) {
            scale *= 0.08838834764831845f;
            qn[(((size_t)(b * HKN + unit)) * SS + s) * 128 + d] = xs * scale;
        } else {
            kn[(((size_t)(b * HKN + unit - 16)) * SS + s) * 128 + d] = xs * scale;
        }
    } else {
        vout[(((size_t)(b * HVN + unit - 32)) * SS + s) * 128 + d] = xs;
    }
}

// ---------------- chunked gated delta rule, DV split x2 ----------------
#define DELTA_SMEM_BYTES ((8192+8320+8192+4096+4096+4096+256)*4)

__global__ __launch_bounds__(256, 1) void delta_kernel(
    const float* __restrict__ qn, const float* __restrict__ kn,
    const float* __restrict__ vv, const float* __restrict__ beta,
    const float* __restrict__ gg, float* __restrict__ core)
{
    extern __shared__ float sm[];
    float* st  = sm;          // [128][64]
    float* KT  = st + 8192;   // [128][65]
    float* Qs  = KT + 8320;   // [64][128]
    float* Vs  = Qs + 8192;   // [64][64]
    float* Wm  = Vs + 4096;   // [64][64]
    float* Am  = Wm + 4096;   // [64][64]
    float* gcs = Am + 4096;
    float* bet = gcs + 64;
    float* egs = bet + 64;
    float* edl = egs + 64;

    int t = threadIdx.x;
    int vs = blockIdx.x & 1;
    int h  = (blockIdx.x >> 1) & 31;
    int b  = blockIdx.x >> 6;
    int vo = vs * 64;
    int hk = h >> 1;
    const float* qb = qn + (size_t)(b*HKN+hk)*SS*128;
    const float* kb = kn + (size_t)(b*HKN+hk)*SS*128;
    const float* vb = vv + (size_t)(b*HVN+h)*SS*128;
    const float* bp = beta + (size_t)b*SS*HVN + h;
    const float* gp = gg   + (size_t)b*SS*HVN + h;
    float* cb = core + (size_t)(b*HVN+h)*SS*128;

    for (int i = t; i < 8192; i += 256) st[i] = 0.f;
    __syncthreads();

    for (int ck = 0; ck < NCHK; ck++) {
        size_t srow = (size_t)ck * 64;
        const float* qr = qb + srow*128;
        const float* kr = kb + srow*128;
        const float* vr = vb + srow*128;
        for (int idx = t; idx < 8192; idx += 256) {
            Qs[idx] = qr[idx];
            int i = idx >> 7, d = idx & 127;
            KT[d*65 + i] = kr[idx];
        }
        for (int idx = t; idx < 4096; idx += 256) {
            int i = idx >> 6, c = idx & 63;
            Vs[idx] = vr[i*128 + vo + c];
        }
        if (t < 64) {
            bet[t] = bp[(srow + t)*HVN];
            edl[t] = gp[(srow + t)*HVN];
        }
        __syncthreads();
        if (t == 0) {
            float r = 0.f;
            for (int i = 0; i < 64; i++) { r += edl[i]; gcs[i] = r; }
        }
        __syncthreads();
        if (t < 64) {
            egs[t] = expf(gcs[t]);
            edl[t] = expf(gcs[63] - gcs[t]);
        }
        __syncthreads();

        {
            int r0 = (t >> 3) * 2, c0 = (t & 7) * 8;
            float wa[2][8], aa[2][8];
#pragma unroll
            for (int i = 0; i < 2; i++)
#pragma unroll
                for (int j = 0; j < 8; j++) { wa[i][j] = 0.f; aa[i][j] = 0.f; }
            for (int d = 0; d < 128; d++) {
                float k0 = KT[d*65 + r0], k1 = KT[d*65 + r0 + 1];
                float q0 = Qs[r0*128 + d], q1 = Qs[(r0+1)*128 + d];
                const float* kj = &KT[d*65 + c0];
#pragma unroll
                for (int j = 0; j < 8; j++) {
                    float kv = kj[j];
                    wa[0][j] += k0*kv; wa[1][j] += k1*kv;
                    aa[0][j] += q0*kv; aa[1][j] += q1*kv;
                }
            }
#pragma unroll
            for (int ii = 0; ii < 2; ii++) {
                int i = r0 + ii; float bi = bet[i], gi = gcs[i];
#pragma unroll
                for (int j = 0; j < 8; j++) {
                    int jc = c0 + j;
                    float wv = 0.f, av = 0.f;
                    if (jc <= i) {
                        float e = expf(gi - gcs[jc]);
                        av = e * aa[ii][j];
                        if (jc < i) wv = bi * e * wa[ii][j];
                    }
                    Wm[i*64 + jc] = wv;
                    Am[i*64 + jc] = av;
                }
            }
        }
        {
            int r0 = (t >> 3) * 2, c0 = (t & 7) * 8;
            float acc[2][8];
#pragma unroll
            for (int i = 0; i < 2; i++)
#pragma unroll
                for (int j = 0; j < 8; j++) acc[i][j] = 0.f;
            for (int d = 0; d < 128; d++) {
                float kv0 = KT[d*65 + r0], kv1 = KT[d*65 + r0 + 1];
                float4 s0 = *(float4*)&st[d*64 + c0];
                float4 s1 = *(float4*)&st[d*64 + c0 + 4];
                float sv[8] = {s0.x,s0.y,s0.z,s0.w,s1.x,s1.y,s1.z,s1.w};
#pragma unroll
                for (int j = 0; j < 8; j++) {
                    acc[0][j] += kv0*sv[j];
                    acc[1][j] += kv1*sv[j];
                }
            }
            __syncthreads();
#pragma unroll
            for (int i = 0; i < 2; i++) {
                int r = r0 + i; float bi = bet[r], e = egs[r];
#pragma unroll
                for (int j = 0; j < 8; j++) {
                    int c = c0 + j;
                    Vs[r*64 + c] = bi*(Vs[r*64 + c] - e*acc[i][j]);
                }
            }
        }
        __syncthreads();
        if (t < 64) {
            float x[64];
#pragma unroll
            for (int i = 0; i < 64; i++) {
                float a0 = Vs[i*64 + t], a1 = 0.f;
                int j = 0;
#pragma unroll
                for (; j + 2 <= i; j += 2) {
                    a0 -= Wm[i*64 + j]   * x[j];
                    a1 -= Wm[i*64 + j+1] * x[j+1];
                }
                if (j < i) a0 -= Wm[i*64 + j] * x[j];
                x[i] = a0 + a1;
            }
#pragma unroll
            for (int i = 0; i < 64; i++) Vs[i*64 + t] = x[i];
        }
        __syncthreads();
        {
            int r0 = (t >> 3) * 2, c0 = (t & 7) * 8;
            float o1[2][8], o2[2][8];
#pragma unroll
            for (int i = 0; i < 2; i++)
#pragma unroll
                for (int j = 0; j < 8; j++) { o1[i][j] = 0.f; o2[i][j] = 0.f; }
            for (int d = 0; d < 128; d++) {
                float q0 = Qs[r0*128 + d], q1 = Qs[(r0+1)*128 + d];
                float4 s0 = *(float4*)&st[d*64 + c0];
                float4 s1 = *(float4*)&st[d*64 + c0 + 4];
                float sv[8] = {s0.x,s0.y,s0.z,s0.w,s1.x,s1.y,s1.z,s1.w};
#pragma unroll
                for (int j = 0; j < 8; j++) {
                    o1[0][j] += q0*sv[j];
                    o1[1][j] += q1*sv[j];
                }
            }
            for (int jj = 0; jj < 64; jj++) {
                float a0 = Am[r0*64 + jj], a1 = Am[(r0+1)*64 + jj];
                float4 v0 = *(float4*)&Vs[jj*64 + c0];
                float4 v1 = *(float4*)&Vs[jj*64 + c0 + 4];
                float vw[8] = {v0.x,v0.y,v0.z,v0.w,v1.x,v1.y,v1.z,v1.w};
#pragma unroll
                for (int j = 0; j < 8; j++) {
                    o2[0][j] += a0*vw[j];
                    o2[1][j] += a1*vw[j];
                }
            }
#pragma unroll
            for (int i = 0; i < 2; i++) {
                int r = r0 + i; float e = egs[r];
#pragma unroll
                for (int j = 0; j < 8; j += 4) {
                    float4 v;
                    v.x = e*o1[i][j]   + o2[i][j];
                    v.y = e*o1[i][j+1] + o2[i][j+1];
                    v.z = e*o1[i][j+2] + o2[i][j+2];
                    v.w = e*o1[i][j+3] + o2[i][j+3];
                    *(float4*)&cb[(srow + r)*128 + vo + c0 + j] = v;
                }
            }
        }
        __syncthreads();
        {
            int d0 = (t >> 3) * 4, v0 = (t & 7) * 8;
            float acc[4][8];
#pragma unroll
            for (int i = 0; i < 4; i++)
#pragma unroll
                for (int j = 0; j < 8; j++) acc[i][j] = 0.f;
            for (int i = 0; i < 64; i++) {
                float el = edl[i];
                float kv[4];
#pragma unroll
                for (int x2 = 0; x2 < 4; x2++) kv[x2] = KT[(d0+x2)*65 + i] * el;
                float4 a = *(float4*)&Vs[i*64 + v0];
                float4 bq = *(float4*)&Vs[i*64 + v0 + 4];
                float vw[8] = {a.x,a.y,a.z,a.w,bq.x,bq.y,bq.z,bq.w};
#pragma unroll
                for (int x2 = 0; x2 < 4; x2++)
#pragma unroll
                    for (int y = 0; y < 8; y++) acc[x2][y] += kv[x2]*vw[y];
            }
            float egl = expf(gcs[63]);
#pragma unroll
            for (int x2 = 0; x2 < 4; x2++)
#pragma unroll
                for (int y = 0; y < 8; y += 4) {
                    float4 s = *(float4*)&st[(d0+x2)*64 + v0 + y];
                    s.x = s.x*egl + acc[x2][y];
                    s.y = s.y*egl + acc[x2][y+1];
                    s.z = s.z*egl + acc[x2][y+2];
                    s.w = s.w*egl + acc[x2][y+3];
                    *(float4*)&st[(d0+x2)*64 + v0 + y] = s;
                }
        }
        __syncthreads();
    }
}

// ---------------- gated RMSNorm + SiLU(z) gate -> bf16 hi/lo ----------------
__global__ __launch_bounds__(128) void normgate_kernel(
    const float* __restrict__ core, const float* __restrict__ z,
    const float* __restrict__ norm_weight,
    __nv_bfloat16* __restrict__ act_hi, __nv_bfloat16* __restrict__ act_lo)
{
    int s = blockIdx.x, h = blockIdx.y, b = blockIdx.z;
    int d = threadIdx.x;
    __shared__ float red[4];
    size_t ci = ((size_t)(b*HVN + h)*SS + s)*128 + d;
    float v = core[ci];
    float ss = v*v;
#pragma unroll
    for (int off = 16; off > 0; off >>= 1) ss += __shfl_down_sync(0xffffffffu, ss, off);
    if ((d & 31) == 0) red[d >> 5] = ss;
    __syncthreads();
    float var = (red[0]+red[1]+red[2]+red[3]) * (1.f/128.f);
    float scale = rsqrtf(var + 1e-6f) * norm_weight[d];
    size_t zi = ((size_t)b*SS + s)*VALD + h*128 + d;
    float zv = z[zi];
    float gate = zv / (1.f + expf(-zv));
    float val = v * scale * gate;
    __nv_bfloat16 hv = __float2bfloat16_rn(val);
    act_hi[zi] = hv;
    act_lo[zi] = __float2bfloat16_rn(val - __bfloat162float(hv));
}

extern "C" void kernel_launch(void* const* d_in, const int* in_sizes, int n_in,
                              void* d_out, int out_size) {
    const float* hs     = (const float*)d_in[0];
    const float* W_qkv  = (const float*)d_in[1];
    const float* conv_w = (const float*)d_in[2];
    const float* W_z    = (const float*)d_in[3];
    const float* W_b    = (const float*)d_in[4];
    const float* W_a    = (const float*)d_in[5];
    const float* dt_b   = (const float*)d_in[6];
    const float* A_log  = (const float*)d_in[7];
    const float* normw  = (const float*)d_in[8];
    const float* W_out  = (const float*)d_in[9];
    float* out = (float*)d_out;

    float *mixed, *z, *qn, *kn, *v, *core, *beta, *gg;
    cudaGetSymbolAddress((void**)&mixed, g_mixed);
    cudaGetSymbolAddress((void**)&z,     g_z);
    cudaGetSymbolAddress((void**)&qn,    g_qn);
    cudaGetSymbolAddress((void**)&kn,    g_kn);
    cudaGetSymbolAddress((void**)&v,     g_v);
    cudaGetSymbolAddress((void**)&core,  g_core);
    cudaGetSymbolAddress((void**)&beta,  g_beta);
    cudaGetSymbolAddress((void**)&gg,    g_gg);

    __nv_bfloat16 *hs_hi, *hs_lo, *wqkv_hi, *wqkv_lo, *wz_hi, *wz_lo, *wout_hi, *wout_lo, *act_hi, *act_lo;
    cudaGetSymbolAddress((void**)&hs_hi,   g_hs_hi);
    cudaGetSymbolAddress((void**)&hs_lo,   g_hs_lo);
    cudaGetSymbolAddress((void**)&wqkv_hi, g_wqkv_hi);
    cudaGetSymbolAddress((void**)&wqkv_lo, g_wqkv_lo);
    cudaGetSymbolAddress((void**)&wz_hi,   g_wz_hi);
    cudaGetSymbolAddress((void**)&wz_lo,   g_wz_lo);
    cudaGetSymbolAddress((void**)&wout_hi, g_wout_hi);
    cudaGetSymbolAddress((void**)&wout_lo, g_wout_lo);
    cudaGetSymbolAddress((void**)&act_hi,  g_act_hi);
    cudaGetSymbolAddress((void**)&act_lo,  g_act_lo);

    cudaFuncSetAttribute(delta_kernel, cudaFuncAttributeMaxDynamicSharedMemorySize, DELTA_SMEM_BYTES);
    cudaFuncSetAttribute(hmma_gemm_kernel, cudaFuncAttributeMaxDynamicSharedMemorySize, GEMM_SMEM);

    // side stream + events (created once; identical launch graph every call)
    static cudaStream_t s2 = nullptr;
    static cudaEvent_t e_fork = nullptr, e_g2 = nullptr;
    if (s2 == nullptr) {
        cudaStreamCreateWithFlags(&s2, cudaStreamNonBlocking);
        cudaEventCreateWithFlags(&e_fork, cudaEventDisableTiming);
        cudaEventCreateWithFlags(&e_g2, cudaEventDisableTiming);
    }

    // 0) weight transposes+splits (one launch), hs split
    tsplit_all_kernel<<<32768, 256>>>(W_qkv, wqkv_hi, wqkv_lo, W_z, wz_hi, wz_lo, W_out, wout_hi, wout_lo);
    split_kernel<<<2048, 256>>>(hs, hs_hi, hs_lo, (size_t)MROWS*HIDN);

    // 1) mixed = hs @ W_qkv  (captured profile slot)
    hmma_gemm_kernel<<<dim3(MROWS/128, CONVD/128), 256, GEMM_SMEM>>>(
        hs_hi, hs_lo, wqkv_hi, wqkv_lo, mixed, MROWS, CONVD, HIDN);

    // fork: z-projection runs concurrently with conv+delta chain
    cudaEventRecord(e_fork, 0);
    cudaStreamWaitEvent(s2, e_fork, 0);
    hmma_gemm_kernel<<<dim3(MROWS/128, VALD/128), 256, GEMM_SMEM, s2>>>(
        hs_hi, hs_lo, wz_hi, wz_lo, z, MROWS, VALD, HIDN);
    cudaEventRecord(e_g2, s2);

    // main chain
    bg_kernel<<<MROWS/BG_RG, 256>>>(hs, W_b, W_a, dt_b, A_log, beta, gg);
    conv_silu_kernel<<<dim3(64, SS, BB), 128>>>(mixed, conv_w, qn, kn, v);
    delta_kernel<<<BB*HVN*2, 256, DELTA_SMEM_BYTES>>>(qn, kn, v, beta, gg, core);

    // join: normgate needs z
    cudaStreamWaitEvent(0, e_g2, 0);
    normgate_kernel<<<dim3(SS, HVN, BB), 128>>>(core, z, normw, act_hi, act_lo);

    // 7) out = act @ W_out
    hmma_gemm_kernel<<<dim3(MROWS/128, HIDN/128), 256, GEMM_SMEM>>>(
        act_hi, act_lo, wout_hi, wout_lo, out, MROWS, HIDN, VALD);
}

// round 9
// speedup vs baseline: 2.2558x; 1.0828x over previous
#include <cuda_runtime.h>
#include <cuda_bf16.h>
#include <math.h>
#include <stdint.h>

#define BB    2
#define SS    4096
#define HIDN  2048
#define HVN   32
#define HKN   16
#define CONVD 8192
#define KEYD  2048
#define VALD  4096
#define NCHK  64
#define MROWS (BB*SS)

// ---------------- device scratch ----------------
__device__ float g_mixed[(size_t)BB*SS*CONVD];
__device__ float g_z    [(size_t)BB*SS*VALD];
__device__ float g_qn   [(size_t)BB*HKN*SS*128];
__device__ float g_kn   [(size_t)BB*HKN*SS*128];
__device__ float g_v    [(size_t)BB*HVN*SS*128];
__device__ float g_core [(size_t)BB*HVN*SS*128];
__device__ float g_beta [(size_t)BB*SS*HVN];
__device__ float g_gg   [(size_t)BB*SS*HVN];

__device__ __nv_bfloat16 g_hs_hi [(size_t)MROWS*HIDN];
__device__ __nv_bfloat16 g_hs_lo [(size_t)MROWS*HIDN];
__device__ __nv_bfloat16 g_wqkv_hi[(size_t)CONVD*HIDN];  // [N,K]
__device__ __nv_bfloat16 g_wqkv_lo[(size_t)CONVD*HIDN];
__device__ __nv_bfloat16 g_wz_hi  [(size_t)VALD*HIDN];
__device__ __nv_bfloat16 g_wz_lo  [(size_t)VALD*HIDN];
__device__ __nv_bfloat16 g_wout_hi[(size_t)HIDN*VALD];
__device__ __nv_bfloat16 g_wout_lo[(size_t)HIDN*VALD];
__device__ __nv_bfloat16 g_act_hi [(size_t)MROWS*VALD];
__device__ __nv_bfloat16 g_act_lo [(size_t)MROWS*VALD];

// ---------------- helpers ----------------
__device__ __forceinline__ uint32_t smem_u32(const void* p) {
    uint32_t a;
    asm("{ .reg .u64 t; cvta.to.shared.u64 t, %1; cvt.u32.u64 %0, t; }" : "=r"(a) : "l"(p));
    return a;
}
__device__ __forceinline__ void ldsm4(uint32_t* r, uint32_t addr) {
    asm volatile("ldmatrix.sync.aligned.m8n8.x4.shared.b16 {%0,%1,%2,%3}, [%4];"
        : "=r"(r[0]), "=r"(r[1]), "=r"(r[2]), "=r"(r[3]) : "r"(addr));
}
__device__ __forceinline__ void mma16816(float* c, const uint32_t* a, const uint32_t* b) {
    asm volatile("mma.sync.aligned.m16n8k16.row.col.f32.bf16.bf16.f32 "
        "{%0,%1,%2,%3}, {%4,%5,%6,%7}, {%8,%9}, {%0,%1,%2,%3};"
        : "+f"(c[0]), "+f"(c[1]), "+f"(c[2]), "+f"(c[3])
        : "r"(a[0]), "r"(a[1]), "r"(a[2]), "r"(a[3]), "r"(b[0]), "r"(b[1]));
}
__device__ __forceinline__ void cp16(uint32_t dst, const void* src) {
    asm volatile("cp.async.cg.shared.global [%0], [%1], 16;" :: "r"(dst), "l"(src));
}

// ---------------- split kernels ----------------
__global__ __launch_bounds__(256) void split_kernel(
    const float* __restrict__ in, __nv_bfloat16* __restrict__ hi, __nv_bfloat16* __restrict__ lo, size_t n)
{
    size_t i = (size_t)blockIdx.x * 256 + threadIdx.x;
    size_t stride = (size_t)gridDim.x * 256;
    for (; i < n; i += stride) {
        float v = in[i];
        __nv_bfloat16 h = __float2bfloat16_rn(v);
        hi[i] = h;
        lo[i] = __float2bfloat16_rn(v - __bfloat162float(h));
    }
}

__global__ __launch_bounds__(256) void tsplit_all_kernel(
    const float* __restrict__ Wq, __nv_bfloat16* __restrict__ qh, __nv_bfloat16* __restrict__ ql,
    const float* __restrict__ Wz, __nv_bfloat16* __restrict__ zh, __nv_bfloat16* __restrict__ zl,
    const float* __restrict__ Wo, __nv_bfloat16* __restrict__ oh, __nv_bfloat16* __restrict__ ol)
{
    __shared__ float tile[32][33];
    int n = blockIdx.x;
    const float* W; __nv_bfloat16 *Thi, *Tlo; int K, N, bx, by;
    if (n < 16384)      { W = Wq; Thi = qh; Tlo = ql; K = HIDN; N = CONVD; bx = n & 255; by = n >> 8; }
    else if (n < 24576) { n -= 16384; W = Wz; Thi = zh; Tlo = zl; K = HIDN; N = VALD; bx = n & 127; by = n >> 7; }
    else                { n -= 24576; W = Wo; Thi = oh; Tlo = ol; K = VALD; N = HIDN; bx = n & 63;  by = n >> 6; }
    int tx = threadIdx.x & 31, ty = threadIdx.x >> 5;
    for (int i = ty; i < 32; i += 8)
        tile[i][tx] = W[(size_t)(by*32 + i) * N + bx*32 + tx];
    __syncthreads();
    for (int i = ty; i < 32; i += 8) {
        float v = tile[tx][i];
        __nv_bfloat16 h = __float2bfloat16_rn(v);
        size_t oi = (size_t)(bx*32 + i) * K + by*32 + tx;
        Thi[oi] = h;
        Tlo[oi] = __float2bfloat16_rn(v - __bfloat162float(h));
    }
}

// ---------------- HMMA bf16x3 GEMM: C[M,N] = A @ B^T ----------------
#define GS_ROW   80
#define GS_ARR   (128*GS_ROW)
#define GS_STAGE (4*GS_ARR)
#define GEMM_SMEM (2*GS_STAGE)

__global__ __launch_bounds__(256, 2) void hmma_gemm_kernel(
    const __nv_bfloat16* __restrict__ Ahi, const __nv_bfloat16* __restrict__ Alo,
    const __nv_bfloat16* __restrict__ Bhi, const __nv_bfloat16* __restrict__ Blo,
    float* __restrict__ C, int M, int N, int K)
{
    extern __shared__ char smem[];
    uint32_t sb = smem_u32(smem);
    int t = threadIdx.x;
    int m0 = blockIdx.x * 128;
    int n0 = blockIdx.y * 128;
    int w = t >> 5, l = t & 31;
    int wm = w & 3, wn = w >> 2;

    const __nv_bfloat16* srcs[4] = { Ahi, Alo, Bhi, Blo };
    int rowbase[4];
    rowbase[0] = m0; rowbase[1] = m0; rowbase[2] = n0; rowbase[3] = n0;

    float acc[2][8][4];
#pragma unroll
    for (int i = 0; i < 2; i++)
#pragma unroll
        for (int j = 0; j < 8; j++)
#pragma unroll
            for (int r = 0; r < 4; r++) acc[i][j][r] = 0.f;

    int KT = K >> 5;

    auto load_stage = [&](int s, int k0) {
        uint32_t stb = sb + s * GS_STAGE;
#pragma unroll
        for (int c = 0; c < 8; c++) {
            int idx = t + c * 256;
            int arr = idx >> 9;
            int within = idx & 511;
            int row = within >> 2, ch = within & 3;
            const __nv_bfloat16* src = srcs[arr] + (size_t)(rowbase[arr] + row) * K + k0 + ch * 8;
            cp16(stb + arr * GS_ARR + row * GS_ROW + ch * 16, src);
        }
        asm volatile("cp.async.commit_group;");
    };

    load_stage(0, 0);

    int a_off = (wm * 32 + (l & 15)) * GS_ROW + ((l >> 4) * 16);
    int b_off = (wn * 64 + (l & 7) + ((l >> 4) << 3)) * GS_ROW + (((l >> 3) & 1) * 16);

    for (int kt = 0; kt < KT; kt++) {
        if (kt + 1 < KT) load_stage((kt + 1) & 1, (kt + 1) << 5);
        if (kt + 1 < KT) asm volatile("cp.async.wait_group 1;");
        else             asm volatile("cp.async.wait_group 0;");
        __syncthreads();

        uint32_t stb = sb + (kt & 1) * GS_STAGE;
#pragma unroll
        for (int ks = 0; ks < 2; ks++) {
            uint32_t ah[2][4], al[2][4];
#pragma unroll
            for (int mt = 0; mt < 2; mt++) {
                uint32_t aa = stb + a_off + mt * 16 * GS_ROW + ks * 32;
                ldsm4(ah[mt], aa);
                ldsm4(al[mt], aa + GS_ARR);
            }
#pragma unroll
            for (int ntp = 0; ntp < 4; ntp++) {
                uint32_t ba = stb + 2 * GS_ARR + b_off + ntp * 16 * GS_ROW + ks * 32;
                uint32_t bh[4], bl[4];
                ldsm4(bh, ba);
                ldsm4(bl, ba + GS_ARR);
#pragma unroll
                for (int mt = 0; mt < 2; mt++) {
                    mma16816(acc[mt][2*ntp],   ah[mt], bh);
                    mma16816(acc[mt][2*ntp],   ah[mt], bl);
                    mma16816(acc[mt][2*ntp],   al[mt], bh);
                    mma16816(acc[mt][2*ntp+1], ah[mt], bh + 2);
                    mma16816(acc[mt][2*ntp+1], ah[mt], bl + 2);
                    mma16816(acc[mt][2*ntp+1], al[mt], bh + 2);
                }
            }
        }
        __syncthreads();
    }

#pragma unroll
    for (int mt = 0; mt < 2; mt++) {
        int row = m0 + wm * 32 + mt * 16 + (l >> 2);
        int colb = n0 + wn * 64 + 2 * (l & 3);
#pragma unroll
        for (int nt = 0; nt < 8; nt++) {
            int col = colb + nt * 8;
            float2 v0; v0.x = acc[mt][nt][0]; v0.y = acc[mt][nt][1];
            float2 v1; v1.x = acc[mt][nt][2]; v1.y = acc[mt][nt][3];
            *(float2*)&C[(size_t)row * N + col] = v0;
            *(float2*)&C[(size_t)(row + 8) * N + col] = v1;
        }
    }
}

// ---------------- beta / g projections ----------------
#define BG_RG 4
__global__ __launch_bounds__(256) void bg_kernel(
    const float* __restrict__ hs, const float* __restrict__ W_b, const float* __restrict__ W_a,
    const float* __restrict__ dt_bias, const float* __restrict__ A_log,
    float* __restrict__ beta, float* __restrict__ gg)
{
    __shared__ float hsm[BG_RG * HIDN];
    __shared__ float red[4 * BG_RG * 64];
    int r0 = blockIdx.x * BG_RG;
    int t = threadIdx.x;
    for (int o = t; o < BG_RG * HIDN / 4; o += 256)
        ((float4*)hsm)[o] = ((const float4*)(hs + (size_t)r0 * HIDN))[o];
    __syncthreads();

    int out = t & 63, part = t >> 6;
    const float* Wp = (out < 32) ? (W_b + out) : (W_a + out - 32);
    float acc[BG_RG];
#pragma unroll
    for (int r = 0; r < BG_RG; r++) acc[r] = 0.f;
    int kbase = part * (HIDN / 4);
    for (int kk = 0; kk < HIDN / 4; kk++) {
        int k = kbase + kk;
        float w2 = Wp[(size_t)k * 32];
#pragma unroll
        for (int r = 0; r < BG_RG; r++) acc[r] += hsm[r * HIDN + k] * w2;
    }
#pragma unroll
    for (int r = 0; r < BG_RG; r++) red[(part * BG_RG + r) * 64 + out] = acc[r];
    __syncthreads();

    int rr = t >> 6, oo = t & 63;
    float s = red[(0*BG_RG+rr)*64+oo] + red[(1*BG_RG+rr)*64+oo]
            + red[(2*BG_RG+rr)*64+oo] + red[(3*BG_RG+rr)*64+oo];
    size_t row = (size_t)r0 + rr;
    if (oo < 32) {
        beta[row * 32 + oo] = 1.f / (1.f + expf(-s));
    } else {
        int h = oo - 32;
        float x = s + dt_bias[h];
        float sp = (x > 20.f) ? x : log1pf(expf(x));
        gg[row * 32 + h] = -expf(A_log[h]) * sp;
    }
}

// ---------------- conv1d(K=4 causal) + SiLU + split + l2norm(q,k) ----------------
// 8 sequence positions per block; sliding-window register taps
__global__ __launch_bounds__(128) void conv_silu_kernel(
    const float* __restrict__ mixed, const float* __restrict__ conv_w,
    float* __restrict__ qn, float* __restrict__ kn, float* __restrict__ vout)
{
    int unit = blockIdx.x;
    int s0 = blockIdx.y * 8;
    int b = blockIdx.z;
    int d = threadIdx.x;
    int base = (unit < 16) ? unit * 128
             : (unit < 32) ? KEYD + (unit - 16) * 128
             : 2 * KEYD + (unit - 32) * 128;
    int c = base + d;
    const float* mb = mixed + (size_t)b * SS * CONVD + c;

    float m[11];
#pragma unroll
    for (int j = 0; j < 11; j++) {
        int sp = s0 + j - 3;
        m[j] = (sp >= 0) ? mb[(size_t)sp * CONVD] : 0.f;
    }
    float w0 = conv_w[(size_t)c*4+0], w1 = conv_w[(size_t)c*4+1],
          w2 = conv_w[(size_t)c*4+2], w3 = conv_w[(size_t)c*4+3];
    float xs[8];
#pragma unroll
    for (int sp = 0; sp < 8; sp++) {
        float a = w0*m[sp] + w1*m[sp+1] + w2*m[sp+2] + w3*m[sp+3];
        xs[sp] = a / (1.f + expf(-a));
    }

    if (unit < 32) {
        __shared__ float red[8][4];
#pragma unroll
        for (int sp = 0; sp < 8; sp++) {
            float ss = xs[sp]*xs[sp];
#pragma unroll
            for (int off = 16; off > 0; off >>= 1) ss += __shfl_down_sync(0xffffffffu, ss, off);
            if ((d & 31) == 0) red[sp][d >> 5] = ss;
        }
        __syncthreads();
        float* dst; float extra;
        if (unit < 16) { dst = qn + (((size_t)(b*HKN+unit))*SS)*128; extra = 0.08838834764831845f; }
        else           { dst = kn + (((size_t)(b*HKN+unit-16))*SS)*128; extra = 1.f; }
#pragma unroll
        for (int sp = 0; sp < 8; sp++) {
            float tot = red[sp][0]+red[sp][1]+red[sp][2]+red[sp][3];
            float scale = rsqrtf(tot + 1e-6f) * extra;
            dst[(size_t)(s0+sp)*128 + d] = xs[sp] * scale;
        }
    } else {
        float* dst = vout + (((size_t)(b*HVN+unit-32))*SS)*128;
#pragma unroll
        for (int sp = 0; sp < 8; sp++)
            dst[(size_t)(s0+sp)*128 + d] = xs[sp];
    }
}

// ---------------- chunked gated delta rule, DV split x2, W/A on tensor cores ----------------
// fp32 smem: st 8192 | KT 8320 | Qs 8192 | Vs 4096 | Wm 4096 | Am 4096 | scalars 256 = 148992 B
// bf16 smem (after): Khi,Klo,Qhi,Qlo each 64 rows x 272B = 17408 B -> 69632 B
#define DBF_OFF   148992
#define DBF_ARR   17408
#define DBF_PITCH 272
#define DELTA_SMEM_BYTES (148992 + 4*DBF_ARR)

__global__ __launch_bounds__(256, 1) void delta_kernel(
    const float* __restrict__ qn, const float* __restrict__ kn,
    const float* __restrict__ vv, const float* __restrict__ beta,
    const float* __restrict__ gg, float* __restrict__ core)
{
    extern __shared__ float sm[];
    char* smc = (char*)sm;
    uint32_t sbase = smem_u32(sm);
    float* st  = sm;          // [128][64]
    float* KT  = st + 8192;   // [128][65]
    float* Qs  = KT + 8320;   // [64][128]
    float* Vs  = Qs + 8192;   // [64][64]
    float* Wm  = Vs + 4096;   // [64][64]
    float* Am  = Wm + 4096;   // [64][64]
    float* gcs = Am + 4096;
    float* bet = gcs + 64;
    float* egs = bet + 64;
    float* edl = egs + 64;

    int t = threadIdx.x;
    int wrp = t >> 5, l = t & 31;
    int vs = blockIdx.x & 1;
    int h  = (blockIdx.x >> 1) & 31;
    int b  = blockIdx.x >> 6;
    int vo = vs * 64;
    int hk = h >> 1;
    const float* qb = qn + (size_t)(b*HKN+hk)*SS*128;
    const float* kb = kn + (size_t)(b*HKN+hk)*SS*128;
    const float* vb = vv + (size_t)(b*HVN+h)*SS*128;
    const float* bp = beta + (size_t)b*SS*HVN + h;
    const float* gp = gg   + (size_t)b*SS*HVN + h;
    float* cb = core + (size_t)(b*HVN+h)*SS*128;

    for (int i = t; i < 8192; i += 256) st[i] = 0.f;
    __syncthreads();

    for (int ck = 0; ck < NCHK; ck++) {
        size_t srow = (size_t)ck * 64;
        const float* qr = qb + srow*128;
        const float* kr = kb + srow*128;
        const float* vr = vb + srow*128;
        for (int idx = t; idx < 8192; idx += 256) {
            int i = idx >> 7, d = idx & 127;
            float kvv = kr[idx];
            float qvv = qr[idx];
            KT[d*65 + i] = kvv;
            Qs[idx] = qvv;
            __nv_bfloat16 kh = __float2bfloat16_rn(kvv);
            __nv_bfloat16 qh = __float2bfloat16_rn(qvv);
            int ro = i*DBF_PITCH + d*2;
            *(__nv_bfloat16*)(smc + DBF_OFF + 0*DBF_ARR + ro) = kh;
            *(__nv_bfloat16*)(smc + DBF_OFF + 1*DBF_ARR + ro) = __float2bfloat16_rn(kvv - __bfloat162float(kh));
            *(__nv_bfloat16*)(smc + DBF_OFF + 2*DBF_ARR + ro) = qh;
            *(__nv_bfloat16*)(smc + DBF_OFF + 3*DBF_ARR + ro) = __float2bfloat16_rn(qvv - __bfloat162float(qh));
        }
        for (int idx = t; idx < 4096; idx += 256) {
            int i = idx >> 6, c = idx & 63;
            Vs[idx] = vr[i*128 + vo + c];
        }
        if (t < 64) {
            bet[t] = bp[(srow + t)*HVN];
            edl[t] = gp[(srow + t)*HVN];
        }
        __syncthreads();
        if (t == 0) {
            float r = 0.f;
            for (int i = 0; i < 64; i++) { r += edl[i]; gcs[i] = r; }
        }
        __syncthreads();
        if (t < 64) {
            egs[t] = expf(gcs[t]);
            edl[t] = expf(gcs[63] - gcs[t]);
        }
        __syncthreads();

        // ---- W = beta*K.K^T*decay (strict lower), A = Q.K^T*decay (lower) via HMMA bf16x3
        {
            float acc[2][4][4];
#pragma unroll
            for (int a1 = 0; a1 < 2; a1++)
#pragma unroll
                for (int a2 = 0; a2 < 4; a2++)
#pragma unroll
                    for (int a3 = 0; a3 < 4; a3++) acc[a1][a2][a3] = 0.f;

            uint32_t a_row = (l & 15);
            uint32_t a_col = (l >> 4) * 16;
            uint32_t b_row = (l & 7) + ((l >> 4) << 3);
            uint32_t b_col = ((l >> 3) & 1) * 16;
#pragma unroll
            for (int tt = 0; tt < 2; tt++) {
                int tile = wrp + tt*8;
                int Dsel = tile >> 3;       // 0 -> Wm (K.K^T), 1 -> Am (Q.K^T)
                int sub = tile & 7;
                int r0 = (sub >> 1) << 4, c0g = (sub & 1) << 5;
                uint32_t ahb = sbase + DBF_OFF + (Dsel ? 2*DBF_ARR : 0);
#pragma unroll
                for (int kt = 0; kt < 8; kt++) {
                    uint32_t aaddr = ahb + (r0 + a_row)*DBF_PITCH + kt*32 + a_col;
                    uint32_t ah[4], al[4];
                    ldsm4(ah, aaddr);
                    ldsm4(al, aaddr + DBF_ARR);
#pragma unroll
                    for (int nn = 0; nn < 2; nn++) {
                        uint32_t baddr = sbase + DBF_OFF + (c0g + nn*16 + b_row)*DBF_PITCH + kt*32 + b_col;
                        uint32_t bh[4], bl[4];
                        ldsm4(bh, baddr);
                        ldsm4(bl, baddr + DBF_ARR);
                        mma16816(acc[tt][2*nn],   ah, bh);
                        mma16816(acc[tt][2*nn],   ah, bl);
                        mma16816(acc[tt][2*nn],   al, bh);
                        mma16816(acc[tt][2*nn+1], ah, bh + 2);
                        mma16816(acc[tt][2*nn+1], ah, bl + 2);
                        mma16816(acc[tt][2*nn+1], al, bh + 2);
                    }
                }
                // epilogue: decay/beta mask, write Wm or Am
#pragma unroll
                for (int n8 = 0; n8 < 4; n8++) {
#pragma unroll
                    for (int e = 0; e < 4; e++) {
                        int row = r0 + (l >> 2) + ((e >> 1) ? 8 : 0);
                        int col = c0g + n8*8 + 2*(l & 3) + (e & 1);
                        float dot = acc[tt][n8][e];
                        if (Dsel == 0) {
                            float outv = 0.f;
                            if (col < row) outv = bet[row] * expf(gcs[row] - gcs[col]) * dot;
                            Wm[row*64 + col] = outv;
                        } else {
                            float outv = 0.f;
                            if (col <= row) outv = expf(gcs[row] - gcs[col]) * dot;
                            Am[row*64 + col] = outv;
                        }
                    }
                }
            }
        }
        // ---- X = beta*(v - e^{gc} * (k @ st))  (overwrite Vs, [64][64]) ----
        {
            int r0 = (t >> 3) * 2, c0 = (t & 7) * 8;
            float acc[2][8];
#pragma unroll
            for (int i = 0; i < 2; i++)
#pragma unroll
                for (int j = 0; j < 8; j++) acc[i][j] = 0.f;
            for (int d = 0; d < 128; d++) {
                float kv0 = KT[d*65 + r0], kv1 = KT[d*65 + r0 + 1];
                float4 s0 = *(float4*)&st[d*64 + c0];
                float4 s1 = *(float4*)&st[d*64 + c0 + 4];
                float sv[8] = {s0.x,s0.y,s0.z,s0.w,s1.x,s1.y,s1.z,s1.w};
#pragma unroll
                for (int j = 0; j < 8; j++) {
                    acc[0][j] += kv0*sv[j];
                    acc[1][j] += kv1*sv[j];
                }
            }
            __syncthreads();
#pragma unroll
            for (int i = 0; i < 2; i++) {
                int r = r0 + i; float bi = bet[r], e = egs[r];
#pragma unroll
                for (int j = 0; j < 8; j++) {
                    int c = c0 + j;
                    Vs[r*64 + c] = bi*(Vs[r*64 + c] - e*acc[i][j]);
                }
            }
        }
        __syncthreads();
        // ---- forward substitution: v_new = (I+W)^{-1} X, 64 columns ----
        if (t < 64) {
            float x[64];
#pragma unroll
            for (int i = 0; i < 64; i++) {
                float a0 = Vs[i*64 + t], a1 = 0.f;
                int j = 0;
#pragma unroll
                for (; j + 2 <= i; j += 2) {
                    a0 -= Wm[i*64 + j]   * x[j];
                    a1 -= Wm[i*64 + j+1] * x[j+1];
                }
                if (j < i) a0 -= Wm[i*64 + j] * x[j];
                x[i] = a0 + a1;
            }
#pragma unroll
            for (int i = 0; i < 64; i++) Vs[i*64 + t] = x[i];
        }
        __syncthreads();
        // ---- out = e^{gc} * (q @ st) + Am @ v_new ----
        {
            int r0 = (t >> 3) * 2, c0 = (t & 7) * 8;
            float o1[2][8], o2[2][8];
#pragma unroll
            for (int i = 0; i < 2; i++)
#pragma unroll
                for (int j = 0; j < 8; j++) { o1[i][j] = 0.f; o2[i][j] = 0.f; }
            for (int d = 0; d < 128; d++) {
                float q0 = Qs[r0*128 + d], q1 = Qs[(r0+1)*128 + d];
                float4 s0 = *(float4*)&st[d*64 + c0];
                float4 s1 = *(float4*)&st[d*64 + c0 + 4];
                float sv[8] = {s0.x,s0.y,s0.z,s0.w,s1.x,s1.y,s1.z,s1.w};
#pragma unroll
                for (int j = 0; j < 8; j++) {
                    o1[0][j] += q0*sv[j];
                    o1[1][j] += q1*sv[j];
                }
            }
            for (int jj = 0; jj < 64; jj++) {
                float a0 = Am[r0*64 + jj], a1 = Am[(r0+1)*64 + jj];
                float4 v0 = *(float4*)&Vs[jj*64 + c0];
                float4 v1 = *(float4*)&Vs[jj*64 + c0 + 4];
                float vw[8] = {v0.x,v0.y,v0.z,v0.w,v1.x,v1.y,v1.z,v1.w};
#pragma unroll
                for (int j = 0; j < 8; j++) {
                    o2[0][j] += a0*vw[j];
                    o2[1][j] += a1*vw[j];
                }
            }
#pragma unroll
            for (int i = 0; i < 2; i++) {
                int r = r0 + i; float e = egs[r];
#pragma unroll
                for (int j = 0; j < 8; j += 4) {
                    float4 v;
                    v.x = e*o1[i][j]   + o2[i][j];
                    v.y = e*o1[i][j+1] + o2[i][j+1];
                    v.z = e*o1[i][j+2] + o2[i][j+2];
                    v.w = e*o1[i][j+3] + o2[i][j+3];
                    *(float4*)&cb[(srow + r)*128 + vo + c0 + j] = v;
                }
            }
        }
        __syncthreads();
        // ---- state update: st = st*e^{gl} + (k*edl)^T @ v_new  [128][64] ----
        {
            int d0 = (t >> 3) * 4, v0 = (t & 7) * 8;
            float acc[4][8];
#pragma unroll
            for (int i = 0; i < 4; i++)
#pragma unroll
                for (int j = 0; j < 8; j++) acc[i][j] = 0.f;
            for (int i = 0; i < 64; i++) {
                float el = edl[i];
                float kv[4];
#pragma unroll
                for (int x2 = 0; x2 < 4; x2++) kv[x2] = KT[(d0+x2)*65 + i] * el;
                float4 a = *(float4*)&Vs[i*64 + v0];
                float4 bq = *(float4*)&Vs[i*64 + v0 + 4];
                float vw[8] = {a.x,a.y,a.z,a.w,bq.x,bq.y,bq.z,bq.w};
#pragma unroll
                for (int x2 = 0; x2 < 4; x2++)
#pragma unroll
                    for (int y = 0; y < 8; y++) acc[x2][y] += kv[x2]*vw[y];
            }
            float egl = expf(gcs[63]);
#pragma unroll
            for (int x2 = 0; x2 < 4; x2++)
#pragma unroll
                for (int y = 0; y < 8; y += 4) {
                    float4 s = *(float4*)&st[(d0+x2)*64 + v0 + y];
                    s.x = s.x*egl + acc[x2][y];
                    s.y = s.y*egl + acc[x2][y+1];
                    s.z = s.z*egl + acc[x2][y+2];
                    s.w = s.w*egl + acc[x2][y+3];
                    *(float4*)&st[(d0+x2)*64 + v0 + y] = s;
                }
        }
        __syncthreads();
    }
}

// ---------------- gated RMSNorm + SiLU(z) gate -> bf16 hi/lo ----------------
__global__ __launch_bounds__(128) void normgate_kernel(
    const float* __restrict__ core, const float* __restrict__ z,
    const float* __restrict__ norm_weight,
    __nv_bfloat16* __restrict__ act_hi, __nv_bfloat16* __restrict__ act_lo)
{
    int s = blockIdx.x, h = blockIdx.y, b = blockIdx.z;
    int d = threadIdx.x;
    __shared__ float red[4];
    size_t ci = ((size_t)(b*HVN + h)*SS + s)*128 + d;
    float v = core[ci];
    float ss = v*v;
#pragma unroll
    for (int off = 16; off > 0; off >>= 1) ss += __shfl_down_sync(0xffffffffu, ss, off);
    if ((d & 31) == 0) red[d >> 5] = ss;
    __syncthreads();
    float var = (red[0]+red[1]+red[2]+red[3]) * (1.f/128.f);
    float scale = rsqrtf(var + 1e-6f) * norm_weight[d];
    size_t zi = ((size_t)b*SS + s)*VALD + h*128 + d;
    float zv = z[zi];
    float gate = zv / (1.f + expf(-zv));
    float val = v * scale * gate;
    __nv_bfloat16 hv = __float2bfloat16_rn(val);
    act_hi[zi] = hv;
    act_lo[zi] = __float2bfloat16_rn(val - __bfloat162float(hv));
}

extern "C" void kernel_launch(void* const* d_in, const int* in_sizes, int n_in,
                              void* d_out, int out_size) {
    const float* hs     = (const float*)d_in[0];
    const float* W_qkv  = (const float*)d_in[1];
    const float* conv_w = (const float*)d_in[2];
    const float* W_z    = (const float*)d_in[3];
    const float* W_b    = (const float*)d_in[4];
    const float* W_a    = (const float*)d_in[5];
    const float* dt_b   = (const float*)d_in[6];
    const float* A_log  = (const float*)d_in[7];
    const float* normw  = (const float*)d_in[8];
    const float* W_out  = (const float*)d_in[9];
    float* out = (float*)d_out;

    float *mixed, *z, *qn, *kn, *v, *core, *beta, *gg;
    cudaGetSymbolAddress((void**)&mixed, g_mixed);
    cudaGetSymbolAddress((void**)&z,     g_z);
    cudaGetSymbolAddress((void**)&qn,    g_qn);
    cudaGetSymbolAddress((void**)&kn,    g_kn);
    cudaGetSymbolAddress((void**)&v,     g_v);
    cudaGetSymbolAddress((void**)&core,  g_core);
    cudaGetSymbolAddress((void**)&beta,  g_beta);
    cudaGetSymbolAddress((void**)&gg,    g_gg);

    __nv_bfloat16 *hs_hi, *hs_lo, *wqkv_hi, *wqkv_lo, *wz_hi, *wz_lo, *wout_hi, *wout_lo, *act_hi, *act_lo;
    cudaGetSymbolAddress((void**)&hs_hi,   g_hs_hi);
    cudaGetSymbolAddress((void**)&hs_lo,   g_hs_lo);
    cudaGetSymbolAddress((void**)&wqkv_hi, g_wqkv_hi);
    cudaGetSymbolAddress((void**)&wqkv_lo, g_wqkv_lo);
    cudaGetSymbolAddress((void**)&wz_hi,   g_wz_hi);
    cudaGetSymbolAddress((void**)&wz_lo,   g_wz_lo);
    cudaGetSymbolAddress((void**)&wout_hi, g_wout_hi);
    cudaGetSymbolAddress((void**)&wout_lo, g_wout_lo);
    cudaGetSymbolAddress((void**)&act_hi,  g_act_hi);
    cudaGetSymbolAddress((void**)&act_lo,  g_act_lo);

    cudaFuncSetAttribute(delta_kernel, cudaFuncAttributeMaxDynamicSharedMemorySize, DELTA_SMEM_BYTES);
    cudaFuncSetAttribute(hmma_gemm_kernel, cudaFuncAttributeMaxDynamicSharedMemorySize, GEMM_SMEM);

    static cudaStream_t s2 = nullptr;
    static cudaEvent_t e_fork = nullptr, e_g2 = nullptr;
    if (s2 == nullptr) {
        cudaStreamCreateWithFlags(&s2, cudaStreamNonBlocking);
        cudaEventCreateWithFlags(&e_fork, cudaEventDisableTiming);
        cudaEventCreateWithFlags(&e_g2, cudaEventDisableTiming);
    }

    // 0) weight transposes+splits (one launch), hs split
    tsplit_all_kernel<<<32768, 256>>>(W_qkv, wqkv_hi, wqkv_lo, W_z, wz_hi, wz_lo, W_out, wout_hi, wout_lo);
    split_kernel<<<2048, 256>>>(hs, hs_hi, hs_lo, (size_t)MROWS*HIDN);

    // 1) mixed = hs @ W_qkv
    hmma_gemm_kernel<<<dim3(MROWS/128, CONVD/128), 256, GEMM_SMEM>>>(
        hs_hi, hs_lo, wqkv_hi, wqkv_lo, mixed, MROWS, CONVD, HIDN);

    // fork: z-projection on side stream
    cudaEventRecord(e_fork, 0);
    cudaStreamWaitEvent(s2, e_fork, 0);
    hmma_gemm_kernel<<<dim3(MROWS/128, VALD/128), 256, GEMM_SMEM, s2>>>(
        hs_hi, hs_lo, wz_hi, wz_lo, z, MROWS, VALD, HIDN);
    cudaEventRecord(e_g2, s2);

    // main chain
    bg_kernel<<<MROWS/BG_RG, 256>>>(hs, W_b, W_a, dt_b, A_log, beta, gg);
    conv_silu_kernel<<<dim3(64, SS/8, BB), 128>>>(mixed, conv_w, qn, kn, v);
    delta_kernel<<<BB*HVN*2, 256, DELTA_SMEM_BYTES>>>(qn, kn, v, beta, gg, core);

    // join: normgate needs z
    cudaStreamWaitEvent(0, e_g2, 0);
    normgate_kernel<<<dim3(SS, HVN, BB), 128>>>(core, z, normw, act_hi, act_lo);

    // out = act @ W_out
    hmma_gemm_kernel<<<dim3(MROWS/128, HIDN/128), 256, GEMM_SMEM>>>(
        act_hi, act_lo, wout_hi, wout_lo, out, MROWS, HIDN, VALD);
}